// round 8
// baseline (speedup 1.0000x reference)
#include <cuda_runtime.h>
#include <math.h>
#include <cstdint>

#define NB     32
#define SEQ    240
#define HID    1024
#define NLAYER 8
#define NHEAD  16
#define DHEAD  64
#define NVOCAB 48
#define BS_TOT (NB*SEQ)   // 7680
#define QKVW   3072

// ---------------- device scratch (no allocation allowed) ----------------
__device__ float g_z   [BS_TOT*HID];
__device__ float g_qkv [(long long)BS_TOT*QKVW];   // packed Q|K|V per row
__device__ float g_att [BS_TOT*HID];
__device__ float g_z1  [BS_TOT*HID];
__device__ float g_ffh [BS_TOT*HID];
__device__ float g_pool[NB*HID];
__device__ float g_wqkv[(long long)NLAYER*3*HID*HID];  // [L][3072][1024] transposed
__device__ float g_w12 [(long long)NLAYER*2*HID*HID];  // [L][W1t|W2t]
__device__ float g_bqkv[NLAYER*QKVW];

// ============================ helpers ============================
__device__ __forceinline__ uint32_t smem_u32(const void* p) {
    return (uint32_t)__cvta_generic_to_shared(p);
}
__device__ __forceinline__ void cpa16(uint32_t dst, const void* src) {
    asm volatile("cp.async.cg.shared.global [%0], [%1], 16;" :: "r"(dst), "l"(src));
}
#define CPA_COMMIT() asm volatile("cp.async.commit_group;" ::: "memory")
template<int N> __device__ __forceinline__ void cpa_wait() {
    asm volatile("cp.async.wait_group %0;" :: "n"(N) : "memory");
}

__device__ __forceinline__ void mma_tf32(float* c, const uint32_t* a, uint32_t b0, uint32_t b1) {
    asm volatile(
        "mma.sync.aligned.m16n8k8.row.col.f32.tf32.tf32.f32 "
        "{%0,%1,%2,%3}, {%4,%5,%6,%7}, {%8,%9}, {%0,%1,%2,%3};"
        : "+f"(c[0]), "+f"(c[1]), "+f"(c[2]), "+f"(c[3])
        : "r"(a[0]), "r"(a[1]), "r"(a[2]), "r"(a[3]), "r"(b0), "r"(b1));
}

// ============================ weight transpose ============================
// dst[n*HID + k] = src[k*HID + n]; src z-stride = HID*HID, dst z-stride = dstZ.
__global__ void transpose_kernel(const float* __restrict__ src, float* __restrict__ dst,
                                 long long dstZ) {
    __shared__ float t[32][33];
    long long smoff = (long long)blockIdx.z * HID * HID;
    long long dmoff = (long long)blockIdx.z * dstZ;
    int x0 = blockIdx.x * 32, y0 = blockIdx.y * 32;
    int tx = threadIdx.x, ty = threadIdx.y;  // 32 x 8
#pragma unroll
    for (int j = 0; j < 32; j += 8)
        t[ty + j][tx] = src[smoff + (long long)(y0 + ty + j) * HID + x0 + tx];
    __syncthreads();
#pragma unroll
    for (int j = 0; j < 32; j += 8)
        dst[dmoff + (long long)(x0 + ty + j) * HID + y0 + tx] = t[tx][ty + j];
}

// bias pack: g_bqkv[l][t*1024+n]
__global__ void biaspack_kernel(const float* __restrict__ bq, const float* __restrict__ bk,
                                const float* __restrict__ bv) {
    int idx = blockIdx.x * 256 + threadIdx.x;
    if (idx >= NLAYER * QKVW) return;
    int l = idx / QKVW, r = idx % QKVW;
    int t = r >> 10, n = r & 1023;
    const float* src = (t == 0) ? bq : (t == 1) ? bk : bv;
    g_bqkv[idx] = src[l * HID + n];
}

// ============================ tf32 mma.sync GEMM ============================
// C[M,N] = A[M,K] @ Wt^T + bias ; A row-major [M,K] (lda=HID), Wt row-major [N,K].
// BM=128, BN=128, BK=16; 256 threads; warp grid 4x2, warp tile 32x64.
// 5-stage cp.async pipeline, ONE __syncthreads per k-iteration, empty-commit drain.
#define BKC   16
#define PADK  20
#define ABYTES (128 * PADK * 4)
#define STAGEB (2 * ABYTES)            // 20480
#define NSTAGE 5
#define GEMM_SMEM (NSTAGE * STAGEB)    // 102400

__device__ __forceinline__ void gemm_load_stage(uint32_t sbase, int s, int kc, int tid,
                                                const float* __restrict__ A,
                                                const float* __restrict__ Bw,
                                                int row0, int col0) {
    uint32_t abase = sbase + s * STAGEB;
    uint32_t bbase = abase + ABYTES;
    const float* Ag = A  + (long long)row0 * HID + kc * BKC;
    const float* Bg = Bw + (long long)col0 * HID + kc * BKC;
#pragma unroll
    for (int j = 0; j < 2; j++) {
        int c = tid + j * 256;
        int r = c >> 2, q = c & 3;
        uint32_t so = (uint32_t)(r * PADK + q * 4) * 4;
        cpa16(abase + so, Ag + (long long)r * HID + q * 4);
        cpa16(bbase + so, Bg + (long long)r * HID + q * 4);
    }
}

template<int ACT>
__global__ __launch_bounds__(256, 2)
void gemm_tc(const float* __restrict__ A, const float* __restrict__ Bw,
             const float* __restrict__ bias, float* __restrict__ C, int ldC) {
    extern __shared__ float smem[];
    const int tid = threadIdx.x;
    const int wid = tid >> 5, lane = tid & 31;
    const int wm = wid & 3, wn = wid >> 2;
    const int grp = lane >> 2, qid = lane & 3;
    const int row0 = blockIdx.y * 128;
    const int col0 = blockIdx.x * 128;
    uint32_t sbase = smem_u32(smem);

    float acc[2][8][4];
#pragma unroll
    for (int mf = 0; mf < 2; mf++)
#pragma unroll
        for (int nf = 0; nf < 8; nf++)
#pragma unroll
            for (int i = 0; i < 4; i++) acc[mf][nf][i] = 0.f;

    const int NKC = HID / BKC;   // 64

    // prologue: stages 0..3 (chunks 0..3), one commit group each
#pragma unroll
    for (int p = 0; p < NSTAGE - 1; p++) {
        gemm_load_stage(sbase, p, p, tid, A, Bw, row0, col0);
        CPA_COMMIT();
    }

    for (int kc = 0; kc < NKC; kc++) {
        int s = kc % NSTAGE;
        cpa_wait<NSTAGE - 2>();        // oldest group (chunk kc) complete
        __syncthreads();               // visibility + WAR guard for stage reuse

        // issue loads for chunk kc+4 into stage (kc+4)%5; ALWAYS commit a group
        int kl = kc + NSTAGE - 1;
        if (kl < NKC)
            gemm_load_stage(sbase, kl % NSTAGE, kl, tid, A, Bw, row0, col0);
        CPA_COMMIT();                  // empty group in drain tail keeps count exact

        const float* sA = smem + s * (STAGEB / 4);
        const float* sB = sA + (ABYTES / 4);
#pragma unroll
        for (int kk = 0; kk < 2; kk++) {
            int k8 = kk * 8;
            uint32_t af[2][4];
#pragma unroll
            for (int mf = 0; mf < 2; mf++) {
                const float* p = sA + (wm * 32 + mf * 16 + grp) * PADK + k8 + qid;
                af[mf][0] = __float_as_uint(p[0]);
                af[mf][1] = __float_as_uint(p[8 * PADK]);
                af[mf][2] = __float_as_uint(p[4]);
                af[mf][3] = __float_as_uint(p[8 * PADK + 4]);
            }
#pragma unroll
            for (int nf = 0; nf < 8; nf++) {
                const float* p = sB + (wn * 64 + nf * 8 + grp) * PADK + k8 + qid;
                uint32_t b0 = __float_as_uint(p[0]);
                uint32_t b1 = __float_as_uint(p[4]);
                mma_tf32(acc[0][nf], af[0], b0, b1);
                mma_tf32(acc[1][nf], af[1], b0, b1);
            }
        }
    }

#pragma unroll
    for (int mf = 0; mf < 2; mf++) {
        int r0 = row0 + wm * 32 + mf * 16 + grp;
#pragma unroll
        for (int nf = 0; nf < 8; nf++) {
            int cg = col0 + wn * 64 + nf * 8 + 2 * qid;
            float bv0 = bias[cg], bv1 = bias[cg + 1];
            float v00 = acc[mf][nf][0] + bv0;
            float v01 = acc[mf][nf][1] + bv1;
            float v10 = acc[mf][nf][2] + bv0;
            float v11 = acc[mf][nf][3] + bv1;
            if (ACT) {
                v00 = 0.5f * v00 * (1.0f + erff(v00 * 0.70710678118654752f));
                v01 = 0.5f * v01 * (1.0f + erff(v01 * 0.70710678118654752f));
                v10 = 0.5f * v10 * (1.0f + erff(v10 * 0.70710678118654752f));
                v11 = 0.5f * v11 * (1.0f + erff(v11 * 0.70710678118654752f));
            }
            *(float2*)&C[(long long)r0 * ldC + cg]       = make_float2(v00, v01);
            *(float2*)&C[(long long)(r0 + 8) * ldC + cg] = make_float2(v10, v11);
        }
    }
}

// ============================ fused flash attention ============================
// One block per (b,h). K[240][68] + Vt[64][244] + per-warp Q stage + per-warp probs.
#define FA_THREADS 512
#define KS_STRIDE  68
#define VT_STRIDE  244
#define FA_KS_FL   (240 * KS_STRIDE)          // 16320
#define FA_VT_FL   (64 * VT_STRIDE)           // 15616
#define FA_QS_FL   (16 * 4 * KS_STRIDE)       // 4352
#define FA_PS_FL   (16 * 4 * 240)             // 15360
#define FA_SMEM    ((FA_KS_FL + FA_VT_FL + FA_QS_FL + FA_PS_FL) * 4)

__global__ __launch_bounds__(FA_THREADS, 1)
void flash_attn(const float* __restrict__ qkv, const int* __restrict__ lengths,
                float* __restrict__ att) {
    extern __shared__ float fs[];
    float* Ks = fs;                       // [240][68]
    float* Vt = Ks + FA_KS_FL;            // [64][244]
    float* Qs = Vt + FA_VT_FL;            // [16][4][68]
    float* Ps = Qs + FA_QS_FL;            // [16][4][240]

    const int bh = blockIdx.x;
    const int b = bh >> 4, h = bh & 15;
    const int tid = threadIdx.x;
    const int w = tid >> 5, lane = tid & 31;
    const int len = lengths[b];
    const float* base = qkv + (long long)b * SEQ * QKVW + h * DHEAD;
    const float scale = 1.0f / 32.0f;

    // stage K (row-major) and V (transposed)
    for (int i = tid; i < 240 * 16; i += FA_THREADS) {
        int s = i >> 4, d4 = i & 15;
        float4 kk = *(const float4*)(base + (long long)s * QKVW + 1024 + d4 * 4);
        float4 vv = *(const float4*)(base + (long long)s * QKVW + 2048 + d4 * 4);
        *(float4*)&Ks[s * KS_STRIDE + d4 * 4] = kk;
        int d = d4 * 4;
        Vt[(d + 0) * VT_STRIDE + s] = vv.x;
        Vt[(d + 1) * VT_STRIDE + s] = vv.y;
        Vt[(d + 2) * VT_STRIDE + s] = vv.z;
        Vt[(d + 3) * VT_STRIDE + s] = vv.w;
    }
    __syncthreads();

    float* Qw = Qs + w * (4 * KS_STRIDE);
    float* Pw = Ps + w * (4 * 240);

    for (int grp = w; grp < 60; grp += 16) {
        const int q0 = grp * 4;
        const int jmax = (q0 + 3) >> 5;

        for (int i = lane; i < 64; i += 32) {
            int r = i >> 4, d4 = i & 15;
            *(float4*)&Qw[r * KS_STRIDE + d4 * 4] =
                *(const float4*)(base + (long long)(q0 + r) * QKVW + d4 * 4);
        }
        __syncwarp();

        float sc[4][8];
#pragma unroll
        for (int r = 0; r < 4; r++)
#pragma unroll
            for (int j = 0; j < 8; j++) sc[r][j] = 0.f;

#pragma unroll
        for (int d4 = 0; d4 < 16; d4++) {
            float4 qa = *(float4*)&Qw[0 * KS_STRIDE + d4 * 4];
            float4 qb = *(float4*)&Qw[1 * KS_STRIDE + d4 * 4];
            float4 qc = *(float4*)&Qw[2 * KS_STRIDE + d4 * 4];
            float4 qd = *(float4*)&Qw[3 * KS_STRIDE + d4 * 4];
            for (int j = 0; j <= jmax; j++) {
                int k = lane + 32 * j;
                float4 kk = *(float4*)&Ks[k * KS_STRIDE + d4 * 4];
                sc[0][j] += qa.x*kk.x + qa.y*kk.y + qa.z*kk.z + qa.w*kk.w;
                sc[1][j] += qb.x*kk.x + qb.y*kk.y + qb.z*kk.z + qb.w*kk.w;
                sc[2][j] += qc.x*kk.x + qc.y*kk.y + qc.z*kk.z + qc.w*kk.w;
                sc[3][j] += qd.x*kk.x + qd.y*kk.y + qd.z*kk.z + qd.w*kk.w;
            }
        }

#pragma unroll
        for (int r = 0; r < 4; r++) {
            int qr = q0 + r;
            float v[8];
            float m = -1e30f;
#pragma unroll
            for (int j = 0; j < 8; j++) {
                int k = lane + 32 * j;
                v[j] = (k <= qr) ? sc[r][j] * scale : -1e30f;
                m = fmaxf(m, v[j]);
            }
#pragma unroll
            for (int off = 16; off > 0; off >>= 1)
                m = fmaxf(m, __shfl_xor_sync(0xffffffff, m, off));
            float ssum = 0.f;
#pragma unroll
            for (int j = 0; j < 8; j++) {
                v[j] = __expf(v[j] - m);
                ssum += v[j];
            }
#pragma unroll
            for (int off = 16; off > 0; off >>= 1)
                ssum += __shfl_xor_sync(0xffffffff, ssum, off);
            float inv = (qr < len) ? (1.0f / ssum) : 0.0f;
#pragma unroll
            for (int j = 0; j < 8; j++) {
                int k = lane + 32 * j;
                if (k < 240) Pw[r * 240 + k] = v[j] * inv;
            }
        }
        __syncwarp();

        float a00 = 0.f, a01 = 0.f, a10 = 0.f, a11 = 0.f;
        float a20 = 0.f, a21 = 0.f, a30 = 0.f, a31 = 0.f;
        const float4* V0 = (const float4*)&Vt[lane * VT_STRIDE];
        const float4* V1 = (const float4*)&Vt[(lane + 32) * VT_STRIDE];
        const float4* P0 = (const float4*)&Pw[0];
        const float4* P1 = (const float4*)&Pw[240];
        const float4* P2 = (const float4*)&Pw[480];
        const float4* P3 = (const float4*)&Pw[720];
        for (int k4 = 0; k4 <= grp; k4++) {
            float4 v0 = V0[k4], v1 = V1[k4];
            float4 p0 = P0[k4], p1 = P1[k4], p2 = P2[k4], p3 = P3[k4];
            a00 += p0.x*v0.x + p0.y*v0.y + p0.z*v0.z + p0.w*v0.w;
            a01 += p0.x*v1.x + p0.y*v1.y + p0.z*v1.z + p0.w*v1.w;
            a10 += p1.x*v0.x + p1.y*v0.y + p1.z*v0.z + p1.w*v0.w;
            a11 += p1.x*v1.x + p1.y*v1.y + p1.z*v1.z + p1.w*v1.w;
            a20 += p2.x*v0.x + p2.y*v0.y + p2.z*v0.z + p2.w*v0.w;
            a21 += p2.x*v1.x + p2.y*v1.y + p2.z*v1.z + p2.w*v1.w;
            a30 += p3.x*v0.x + p3.y*v0.y + p3.z*v0.z + p3.w*v0.w;
            a31 += p3.x*v1.x + p3.y*v1.y + p3.z*v1.z + p3.w*v1.w;
        }
        float* ob = att + (long long)(b * SEQ + q0) * HID + h * DHEAD;
        ob[0 * HID + lane] = a00;  ob[0 * HID + lane + 32] = a01;
        ob[1 * HID + lane] = a10;  ob[1 * HID + lane + 32] = a11;
        ob[2 * HID + lane] = a20;  ob[2 * HID + lane + 32] = a21;
        ob[3 * HID + lane] = a30;  ob[3 * HID + lane + 32] = a31;
        __syncwarp();
    }
}

// ---------------- embedding: argmax + gather + posenc ----------------
__global__ void embed_kernel(const float* __restrict__ x,
                             const float* __restrict__ w_emb,
                             const float* __restrict__ p_emb,
                             const int*   __restrict__ lengths) {
    int bs = blockIdx.x;
    int b = bs / SEQ, s = bs % SEQ;
    __shared__ int s_tok;
    int tid = threadIdx.x;
    if (tid < 32) {
        const float* xp = x + (long long)bs * NVOCAB;
        float bv = -1e30f; int bi = 0;
        for (int c = tid; c < NVOCAB; c += 32) {
            float v = xp[c];
            if (v > bv) { bv = v; bi = c; }
        }
        for (int off = 16; off > 0; off >>= 1) {
            float ov = __shfl_down_sync(0xffffffff, bv, off);
            int   oi = __shfl_down_sync(0xffffffff, bi, off);
            if (ov > bv || (ov == bv && oi < bi)) { bv = ov; bi = oi; }
        }
        if (tid == 0) s_tok = bi;
    }
    __syncthreads();
    int tok = s_tok;
    float valid = (s < lengths[b]) ? 1.0f : 0.0f;
    const float* we = w_emb + (long long)tok * HID;
    const float* pe = p_emb + (long long)s * HID;
    float* zp = g_z + (long long)bs * HID;
    for (int h = tid; h < HID; h += blockDim.x)
        zp[h] = we[h] * valid + pe[h];
}

// ---------------- residual add + LayerNorm ----------------
__global__ void add_ln_kernel(const float* __restrict__ a, const float* __restrict__ r,
                              const float* __restrict__ sc, const float* __restrict__ bi,
                              float* __restrict__ out) {
    int row = blockIdx.x;
    int tid = threadIdx.x;
    const float* ap = a + (long long)row * HID;
    const float* rp = r + (long long)row * HID;
    float v[4];
    float s = 0.f, sq = 0.f;
#pragma unroll
    for (int j = 0; j < 4; j++) {
        int h = tid + j*256;
        v[j] = ap[h] + rp[h];
        s  += v[j];
        sq += v[j]*v[j];
    }
    __shared__ float red1[8], red2[8];
    for (int off = 16; off > 0; off >>= 1) {
        s  += __shfl_xor_sync(0xffffffff, s,  off);
        sq += __shfl_xor_sync(0xffffffff, sq, off);
    }
    int warp = tid >> 5, lane = tid & 31;
    if (lane == 0) { red1[warp] = s; red2[warp] = sq; }
    __syncthreads();
    if (warp == 0) {
        s  = (lane < 8) ? red1[lane] : 0.f;
        sq = (lane < 8) ? red2[lane] : 0.f;
        for (int off = 4; off > 0; off >>= 1) {
            s  += __shfl_xor_sync(0xffffffff, s,  off);
            sq += __shfl_xor_sync(0xffffffff, sq, off);
        }
        if (lane == 0) { red1[0] = s; red2[0] = sq; }
    }
    __syncthreads();
    float mean = red1[0] * (1.0f / HID);
    float var  = red2[0] * (1.0f / HID) - mean * mean;
    float rstd = rsqrtf(var + 1e-5f);
    float* op = out + (long long)row * HID;
#pragma unroll
    for (int j = 0; j < 4; j++) {
        int h = tid + j*256;
        op[h] = (v[j] - mean) * rstd * sc[h] + bi[h];
    }
}

// ---------------- mean-pool ----------------
__global__ void pool_kernel() {
    int b = blockIdx.y;
    int h = blockIdx.x * 256 + threadIdx.x;
    float s = 0.f;
    const float* zp = g_z + (long long)b * SEQ * HID + h;
    for (int si = 0; si < SEQ; si++)
        s += zp[(long long)si * HID];
    g_pool[b * HID + h] = s * (1.0f / SEQ);
}

// ---------------- classifier head + softmax(4) ----------------
__global__ void head_kernel(const float* __restrict__ Wfc, const float* __restrict__ bfc,
                            float* __restrict__ out) {
    int b = blockIdx.x;
    int tid = threadIdx.x;
    float p[4] = {0.f, 0.f, 0.f, 0.f};
    const float* zp = g_pool + b * HID;
    for (int h = tid; h < HID; h += 256) {
        float zv = zp[h];
#pragma unroll
        for (int c = 0; c < 4; c++) p[c] += zv * Wfc[h*4 + c];
    }
    __shared__ float red[4][256];
#pragma unroll
    for (int c = 0; c < 4; c++) red[c][tid] = p[c];
    __syncthreads();
    for (int str = 128; str > 0; str >>= 1) {
        if (tid < str)
#pragma unroll
            for (int c = 0; c < 4; c++) red[c][tid] += red[c][tid + str];
        __syncthreads();
    }
    if (tid == 0) {
        float l[4];
        float m = -1e30f;
#pragma unroll
        for (int c = 0; c < 4; c++) { l[c] = red[c][0] + bfc[c]; m = fmaxf(m, l[c]); }
        float ssum = 0.f;
#pragma unroll
        for (int c = 0; c < 4; c++) { l[c] = __expf(l[c] - m); ssum += l[c]; }
        float inv = 1.0f / ssum;
#pragma unroll
        for (int c = 0; c < 4; c++) out[b*4 + c] = l[c] * inv;
    }
}

// ---------------- host orchestration ----------------
extern "C" void kernel_launch(void* const* d_in, const int* in_sizes, int n_in,
                              void* d_out, int out_size) {
    const float* x     = (const float*)d_in[0];
    const float* w_emb = (const float*)d_in[1];
    const float* p_emb = (const float*)d_in[2];
    const float* Wq    = (const float*)d_in[3];
    const float* bq    = (const float*)d_in[4];
    const float* Wk    = (const float*)d_in[5];
    const float* bk    = (const float*)d_in[6];
    const float* Wv    = (const float*)d_in[7];
    const float* bv    = (const float*)d_in[8];
    const float* W1    = (const float*)d_in[9];
    const float* b1    = (const float*)d_in[10];
    const float* W2    = (const float*)d_in[11];
    const float* b2    = (const float*)d_in[12];
    const float* ln1_s = (const float*)d_in[13];
    const float* ln1_b = (const float*)d_in[14];
    const float* ln2_s = (const float*)d_in[15];
    const float* ln2_b = (const float*)d_in[16];
    const float* Wfc   = (const float*)d_in[17];
    const float* bfc   = (const float*)d_in[18];
    const int*   lengths = (const int*)d_in[19];
    float* out = (float*)d_out;

    float *pz, *pqkv, *patt, *pz1, *pffh, *pwqkv, *pw12, *pbqkv;
    cudaGetSymbolAddress((void**)&pz,    g_z);
    cudaGetSymbolAddress((void**)&pqkv,  g_qkv);
    cudaGetSymbolAddress((void**)&patt,  g_att);
    cudaGetSymbolAddress((void**)&pz1,   g_z1);
    cudaGetSymbolAddress((void**)&pffh,  g_ffh);
    cudaGetSymbolAddress((void**)&pwqkv, g_wqkv);
    cudaGetSymbolAddress((void**)&pw12,  g_w12);
    cudaGetSymbolAddress((void**)&pbqkv, g_bqkv);

    cudaFuncSetAttribute(gemm_tc<0>, cudaFuncAttributeMaxDynamicSharedMemorySize, GEMM_SMEM);
    cudaFuncSetAttribute(gemm_tc<1>, cudaFuncAttributeMaxDynamicSharedMemorySize, GEMM_SMEM);
    cudaFuncSetAttribute(flash_attn, cudaFuncAttributeMaxDynamicSharedMemorySize, FA_SMEM);

    const long long MAT = (long long)HID * HID;

    // transpose weights into packed layouts
    dim3 tgrid(HID/32, HID/32, NLAYER);
    dim3 tblk(32, 8);
    transpose_kernel<<<tgrid, tblk>>>(Wq, pwqkv + 0*MAT, 3*MAT);
    transpose_kernel<<<tgrid, tblk>>>(Wk, pwqkv + 1*MAT, 3*MAT);
    transpose_kernel<<<tgrid, tblk>>>(Wv, pwqkv + 2*MAT, 3*MAT);
    transpose_kernel<<<tgrid, tblk>>>(W1, pw12  + 0*MAT, 2*MAT);
    transpose_kernel<<<tgrid, tblk>>>(W2, pw12  + 1*MAT, 2*MAT);
    biaspack_kernel<<<(NLAYER*QKVW + 255)/256, 256>>>(bq, bk, bv);

    embed_kernel<<<BS_TOT, 256>>>(x, w_emb, p_emb, lengths);

    dim3 qkv_grid(QKVW/128, BS_TOT/128);   // (24, 60)
    dim3 ff_grid(HID/128, BS_TOT/128);     // (8, 60)

    for (int i = 0; i < NLAYER; i++) {
        long long bOff = (long long)i * HID;
        gemm_tc<0><<<qkv_grid, 256, GEMM_SMEM>>>(pz, pwqkv + (long long)i*3*MAT,
                                                 pbqkv + (long long)i*QKVW, pqkv, QKVW);
        flash_attn<<<NB*NHEAD, FA_THREADS, FA_SMEM>>>(pqkv, lengths, patt);
        add_ln_kernel<<<BS_TOT, 256>>>(pz, patt, ln1_s + bOff, ln1_b + bOff, pz1);
        gemm_tc<1><<<ff_grid, 256, GEMM_SMEM>>>(pz1, pw12 + (long long)i*2*MAT,
                                                b1 + bOff, pffh, HID);
        gemm_tc<0><<<ff_grid, 256, GEMM_SMEM>>>(pffh, pw12 + (long long)i*2*MAT + MAT,
                                                b2 + bOff, patt, HID);
        add_ln_kernel<<<BS_TOT, 256>>>(pz1, patt, ln2_s + bOff, ln2_b + bOff, pz);
    }

    pool_kernel<<<dim3(HID/256, NB), 256>>>();
    head_kernel<<<NB, 256>>>(Wfc, bfc, out);
}

// round 9
// speedup vs baseline: 2.2282x; 2.2282x over previous
#include <cuda_runtime.h>
#include <cuda_fp16.h>
#include <math.h>
#include <cstdint>

#define NB     32
#define SEQ    240
#define HID    1024
#define NLAYER 8
#define NHEAD  16
#define DHEAD  64
#define NVOCAB 48
#define BS_TOT (NB*SEQ)   // 7680
#define QKVW   3072

// ---------------- device scratch (no allocation allowed) ----------------
__device__ float  g_z   [BS_TOT*HID];
__device__ __half g_z16 [BS_TOT*HID];
__device__ float  g_qkv [(long long)BS_TOT*QKVW];
__device__ float  g_att [BS_TOT*HID];
__device__ float  g_z1  [BS_TOT*HID];
__device__ __half g_z116[BS_TOT*HID];
__device__ __half g_ffh16[BS_TOT*HID];
__device__ float  g_pool[NB*HID];
__device__ __half g_wqkv16[(long long)NLAYER*3*HID*HID];  // [L][3072][1024] transposed fp16
__device__ __half g_w1216 [(long long)NLAYER*2*HID*HID];  // [L][W1t|W2t] fp16
__device__ float  g_bqkv[NLAYER*QKVW];

// ============================ helpers ============================
__device__ __forceinline__ uint32_t smem_u32(const void* p) {
    return (uint32_t)__cvta_generic_to_shared(p);
}
__device__ __forceinline__ void cpa16(uint32_t dst, const void* src) {
    asm volatile("cp.async.cg.shared.global [%0], [%1], 16;" :: "r"(dst), "l"(src));
}
#define CPA_COMMIT() asm volatile("cp.async.commit_group;" ::: "memory")
template<int N> __device__ __forceinline__ void cpa_wait() {
    asm volatile("cp.async.wait_group %0;" :: "n"(N) : "memory");
}

__device__ __forceinline__ void mma_f16(float* c, const uint32_t* a, uint32_t b0, uint32_t b1) {
    asm volatile(
        "mma.sync.aligned.m16n8k16.row.col.f32.f16.f16.f32 "
        "{%0,%1,%2,%3}, {%4,%5,%6,%7}, {%8,%9}, {%0,%1,%2,%3};"
        : "+f"(c[0]), "+f"(c[1]), "+f"(c[2]), "+f"(c[3])
        : "r"(a[0]), "r"(a[1]), "r"(a[2]), "r"(a[3]), "r"(b0), "r"(b1));
}

// ============================ weight transpose -> fp16 ============================
// dst[n*HID + k] = (half)src[k*HID + n]; dst z-stride dstZ elements.
__global__ void transpose_h_kernel(const float* __restrict__ src, __half* __restrict__ dst,
                                   long long dstZ) {
    __shared__ float t[32][33];
    long long smoff = (long long)blockIdx.z * HID * HID;
    long long dmoff = (long long)blockIdx.z * dstZ;
    int x0 = blockIdx.x * 32, y0 = blockIdx.y * 32;
    int tx = threadIdx.x, ty = threadIdx.y;  // 32 x 8
#pragma unroll
    for (int j = 0; j < 32; j += 8)
        t[ty + j][tx] = src[smoff + (long long)(y0 + ty + j) * HID + x0 + tx];
    __syncthreads();
#pragma unroll
    for (int j = 0; j < 32; j += 8)
        dst[dmoff + (long long)(x0 + ty + j) * HID + y0 + tx] = __float2half(t[tx][ty + j]);
}

// bias pack: g_bqkv[l][t*1024+n]
__global__ void biaspack_kernel(const float* __restrict__ bq, const float* __restrict__ bk,
                                const float* __restrict__ bv) {
    int idx = blockIdx.x * 256 + threadIdx.x;
    if (idx >= NLAYER * QKVW) return;
    int l = idx / QKVW, r = idx % QKVW;
    int t = r >> 10, n = r & 1023;
    const float* src = (t == 0) ? bq : (t == 1) ? bk : bv;
    g_bqkv[idx] = src[l * HID + n];
}

// ============================ fp16 mma.sync GEMM ============================
// C[M,N] = A[M,K] @ Wt^T + bias ; A fp16 row-major [M,K] (lda=HID), Wt fp16 [N,K].
// BM=128, BN=128, BK=32 halves; 256 threads; warp grid 4x2, warp tile 32x64.
// 3-stage cp.async pipeline (proven R7 loop shape).
#define BKC   32                         // k halves per chunk
#define PADH  40                         // halves per smem row (80B, conflict-free)
#define ABYTES (128 * PADH * 2)          // 10240
#define STAGEB (2 * ABYTES)              // 20480
#define NSTAGE 3
#define GEMM_SMEM (NSTAGE * STAGEB)      // 61440

__device__ __forceinline__ void gemm_load_stage(uint32_t sbase, int s, int kc, int tid,
                                                const __half* __restrict__ A,
                                                const __half* __restrict__ Bw,
                                                int row0, int col0) {
    uint32_t abase = sbase + s * STAGEB;
    uint32_t bbase = abase + ABYTES;
    const __half* Ag = A  + (long long)row0 * HID + kc * BKC;
    const __half* Bg = Bw + (long long)col0 * HID + kc * BKC;
#pragma unroll
    for (int j = 0; j < 2; j++) {
        int c = tid + j * 256;           // 0..511
        int r = c >> 2, q = c & 3;       // row 0..127, 16B-chunk 0..3 (8 halves each)
        uint32_t so = (uint32_t)(r * PADH + q * 8) * 2;
        cpa16(abase + so, Ag + (long long)r * HID + q * 8);
        cpa16(bbase + so, Bg + (long long)r * HID + q * 8);
    }
}

// ACT==0: C is float* ; ACT==1: C is __half* (GELU applied)
template<int ACT>
__global__ __launch_bounds__(256, 2)
void gemm_h(const __half* __restrict__ A, const __half* __restrict__ Bw,
            const float* __restrict__ bias, void* __restrict__ Cv, int ldC) {
    extern __shared__ __half smem[];
    const int tid = threadIdx.x;
    const int wid = tid >> 5, lane = tid & 31;
    const int wm = wid & 3, wn = wid >> 2;
    const int grp = lane >> 2, qid = lane & 3;
    const int row0 = blockIdx.y * 128;
    const int col0 = blockIdx.x * 128;
    uint32_t sbase = smem_u32(smem);

    float acc[2][8][4];
#pragma unroll
    for (int mf = 0; mf < 2; mf++)
#pragma unroll
        for (int nf = 0; nf < 8; nf++)
#pragma unroll
            for (int i = 0; i < 4; i++) acc[mf][nf][i] = 0.f;

    const int NKC = HID / BKC;   // 32

    gemm_load_stage(sbase, 0, 0, tid, A, Bw, row0, col0);
    CPA_COMMIT();
    gemm_load_stage(sbase, 1, 1, tid, A, Bw, row0, col0);
    CPA_COMMIT();

    for (int kc = 0; kc < NKC; kc++) {
        int s = kc % NSTAGE;
        if (kc + 2 < NKC)
            gemm_load_stage(sbase, (kc + 2) % NSTAGE, kc + 2, tid, A, Bw, row0, col0);
        CPA_COMMIT();
        cpa_wait<2>();
        __syncthreads();

        const __half* sA = smem + s * (STAGEB / 2);
        const __half* sB = sA + (ABYTES / 2);
#pragma unroll
        for (int kk = 0; kk < 2; kk++) {
            int k16 = kk * 16;
            uint32_t af[2][4];
#pragma unroll
            for (int mf = 0; mf < 2; mf++) {
                const __half* p = sA + (wm * 32 + mf * 16 + grp) * PADH + k16 + qid * 2;
                af[mf][0] = *(const uint32_t*)(p);
                af[mf][1] = *(const uint32_t*)(p + 8 * PADH);
                af[mf][2] = *(const uint32_t*)(p + 8);
                af[mf][3] = *(const uint32_t*)(p + 8 * PADH + 8);
            }
#pragma unroll
            for (int nf = 0; nf < 8; nf++) {
                const __half* p = sB + (wn * 64 + nf * 8 + grp) * PADH + k16 + qid * 2;
                uint32_t b0 = *(const uint32_t*)(p);
                uint32_t b1 = *(const uint32_t*)(p + 8);
                mma_f16(acc[0][nf], af[0], b0, b1);
                mma_f16(acc[1][nf], af[1], b0, b1);
            }
        }
        __syncthreads();
    }

#pragma unroll
    for (int mf = 0; mf < 2; mf++) {
        int r0 = row0 + wm * 32 + mf * 16 + grp;
#pragma unroll
        for (int nf = 0; nf < 8; nf++) {
            int cg = col0 + wn * 64 + nf * 8 + 2 * qid;
            float bv0 = bias[cg], bv1 = bias[cg + 1];
            float v00 = acc[mf][nf][0] + bv0;
            float v01 = acc[mf][nf][1] + bv1;
            float v10 = acc[mf][nf][2] + bv0;
            float v11 = acc[mf][nf][3] + bv1;
            if (ACT) {
                v00 = 0.5f * v00 * (1.0f + erff(v00 * 0.70710678118654752f));
                v01 = 0.5f * v01 * (1.0f + erff(v01 * 0.70710678118654752f));
                v10 = 0.5f * v10 * (1.0f + erff(v10 * 0.70710678118654752f));
                v11 = 0.5f * v11 * (1.0f + erff(v11 * 0.70710678118654752f));
                __half* C = (__half*)Cv;
                *(__half2*)&C[(long long)r0 * ldC + cg]       = __floats2half2_rn(v00, v01);
                *(__half2*)&C[(long long)(r0 + 8) * ldC + cg] = __floats2half2_rn(v10, v11);
            } else {
                float* C = (float*)Cv;
                *(float2*)&C[(long long)r0 * ldC + cg]       = make_float2(v00, v01);
                *(float2*)&C[(long long)(r0 + 8) * ldC + cg] = make_float2(v10, v11);
            }
        }
    }
}

// ============================ fused flash attention (fp32, unchanged) ============================
#define FA_THREADS 512
#define KS_STRIDE  68
#define VT_STRIDE  244
#define FA_KS_FL   (240 * KS_STRIDE)
#define FA_VT_FL   (64 * VT_STRIDE)
#define FA_QS_FL   (16 * 4 * KS_STRIDE)
#define FA_PS_FL   (16 * 4 * 240)
#define FA_SMEM    ((FA_KS_FL + FA_VT_FL + FA_QS_FL + FA_PS_FL) * 4)

__global__ __launch_bounds__(FA_THREADS, 1)
void flash_attn(const float* __restrict__ qkv, const int* __restrict__ lengths,
                float* __restrict__ att) {
    extern __shared__ float fs[];
    float* Ks = fs;
    float* Vt = Ks + FA_KS_FL;
    float* Qs = Vt + FA_VT_FL;
    float* Ps = Qs + FA_QS_FL;

    const int bh = blockIdx.x;
    const int b = bh >> 4, h = bh & 15;
    const int tid = threadIdx.x;
    const int w = tid >> 5, lane = tid & 31;
    const int len = lengths[b];
    const float* base = qkv + (long long)b * SEQ * QKVW + h * DHEAD;
    const float scale = 1.0f / 32.0f;

    for (int i = tid; i < 240 * 16; i += FA_THREADS) {
        int s = i >> 4, d4 = i & 15;
        float4 kk = *(const float4*)(base + (long long)s * QKVW + 1024 + d4 * 4);
        float4 vv = *(const float4*)(base + (long long)s * QKVW + 2048 + d4 * 4);
        *(float4*)&Ks[s * KS_STRIDE + d4 * 4] = kk;
        int d = d4 * 4;
        Vt[(d + 0) * VT_STRIDE + s] = vv.x;
        Vt[(d + 1) * VT_STRIDE + s] = vv.y;
        Vt[(d + 2) * VT_STRIDE + s] = vv.z;
        Vt[(d + 3) * VT_STRIDE + s] = vv.w;
    }
    __syncthreads();

    float* Qw = Qs + w * (4 * KS_STRIDE);
    float* Pw = Ps + w * (4 * 240);

    for (int grp = w; grp < 60; grp += 16) {
        const int q0 = grp * 4;
        const int jmax = (q0 + 3) >> 5;

        for (int i = lane; i < 64; i += 32) {
            int r = i >> 4, d4 = i & 15;
            *(float4*)&Qw[r * KS_STRIDE + d4 * 4] =
                *(const float4*)(base + (long long)(q0 + r) * QKVW + d4 * 4);
        }
        __syncwarp();

        float sc[4][8];
#pragma unroll
        for (int r = 0; r < 4; r++)
#pragma unroll
            for (int j = 0; j < 8; j++) sc[r][j] = 0.f;

#pragma unroll
        for (int d4 = 0; d4 < 16; d4++) {
            float4 qa = *(float4*)&Qw[0 * KS_STRIDE + d4 * 4];
            float4 qb = *(float4*)&Qw[1 * KS_STRIDE + d4 * 4];
            float4 qc = *(float4*)&Qw[2 * KS_STRIDE + d4 * 4];
            float4 qd = *(float4*)&Qw[3 * KS_STRIDE + d4 * 4];
            for (int j = 0; j <= jmax; j++) {
                int k = lane + 32 * j;
                float4 kk = *(float4*)&Ks[k * KS_STRIDE + d4 * 4];
                sc[0][j] += qa.x*kk.x + qa.y*kk.y + qa.z*kk.z + qa.w*kk.w;
                sc[1][j] += qb.x*kk.x + qb.y*kk.y + qb.z*kk.z + qb.w*kk.w;
                sc[2][j] += qc.x*kk.x + qc.y*kk.y + qc.z*kk.z + qc.w*kk.w;
                sc[3][j] += qd.x*kk.x + qd.y*kk.y + qd.z*kk.z + qd.w*kk.w;
            }
        }

#pragma unroll
        for (int r = 0; r < 4; r++) {
            int qr = q0 + r;
            float v[8];
            float m = -1e30f;
#pragma unroll
            for (int j = 0; j < 8; j++) {
                int k = lane + 32 * j;
                v[j] = (k <= qr) ? sc[r][j] * scale : -1e30f;
                m = fmaxf(m, v[j]);
            }
#pragma unroll
            for (int off = 16; off > 0; off >>= 1)
                m = fmaxf(m, __shfl_xor_sync(0xffffffff, m, off));
            float ssum = 0.f;
#pragma unroll
            for (int j = 0; j < 8; j++) {
                v[j] = __expf(v[j] - m);
                ssum += v[j];
            }
#pragma unroll
            for (int off = 16; off > 0; off >>= 1)
                ssum += __shfl_xor_sync(0xffffffff, ssum, off);
            float inv = (qr < len) ? (1.0f / ssum) : 0.0f;
#pragma unroll
            for (int j = 0; j < 8; j++) {
                int k = lane + 32 * j;
                if (k < 240) Pw[r * 240 + k] = v[j] * inv;
            }
        }
        __syncwarp();

        float a00 = 0.f, a01 = 0.f, a10 = 0.f, a11 = 0.f;
        float a20 = 0.f, a21 = 0.f, a30 = 0.f, a31 = 0.f;
        const float4* V0 = (const float4*)&Vt[lane * VT_STRIDE];
        const float4* V1 = (const float4*)&Vt[(lane + 32) * VT_STRIDE];
        const float4* P0 = (const float4*)&Pw[0];
        const float4* P1 = (const float4*)&Pw[240];
        const float4* P2 = (const float4*)&Pw[480];
        const float4* P3 = (const float4*)&Pw[720];
        for (int k4 = 0; k4 <= grp; k4++) {
            float4 v0 = V0[k4], v1 = V1[k4];
            float4 p0 = P0[k4], p1 = P1[k4], p2 = P2[k4], p3 = P3[k4];
            a00 += p0.x*v0.x + p0.y*v0.y + p0.z*v0.z + p0.w*v0.w;
            a01 += p0.x*v1.x + p0.y*v1.y + p0.z*v1.z + p0.w*v1.w;
            a10 += p1.x*v0.x + p1.y*v0.y + p1.z*v0.z + p1.w*v0.w;
            a11 += p1.x*v1.x + p1.y*v1.y + p1.z*v1.z + p1.w*v1.w;
            a20 += p2.x*v0.x + p2.y*v0.y + p2.z*v0.z + p2.w*v0.w;
            a21 += p2.x*v1.x + p2.y*v1.y + p2.z*v1.z + p2.w*v1.w;
            a30 += p3.x*v0.x + p3.y*v0.y + p3.z*v0.z + p3.w*v0.w;
            a31 += p3.x*v1.x + p3.y*v1.y + p3.z*v1.z + p3.w*v1.w;
        }
        float* ob = att + (long long)(b * SEQ + q0) * HID + h * DHEAD;
        ob[0 * HID + lane] = a00;  ob[0 * HID + lane + 32] = a01;
        ob[1 * HID + lane] = a10;  ob[1 * HID + lane + 32] = a11;
        ob[2 * HID + lane] = a20;  ob[2 * HID + lane + 32] = a21;
        ob[3 * HID + lane] = a30;  ob[3 * HID + lane + 32] = a31;
        __syncwarp();
    }
}

// ---------------- embedding: argmax + gather + posenc (fp32 + fp16 copy) ----------------
__global__ void embed_kernel(const float* __restrict__ x,
                             const float* __restrict__ w_emb,
                             const float* __restrict__ p_emb,
                             const int*   __restrict__ lengths) {
    int bs = blockIdx.x;
    int b = bs / SEQ, s = bs % SEQ;
    __shared__ int s_tok;
    int tid = threadIdx.x;
    if (tid < 32) {
        const float* xp = x + (long long)bs * NVOCAB;
        float bv = -1e30f; int bi = 0;
        for (int c = tid; c < NVOCAB; c += 32) {
            float v = xp[c];
            if (v > bv) { bv = v; bi = c; }
        }
        for (int off = 16; off > 0; off >>= 1) {
            float ov = __shfl_down_sync(0xffffffff, bv, off);
            int   oi = __shfl_down_sync(0xffffffff, bi, off);
            if (ov > bv || (ov == bv && oi < bi)) { bv = ov; bi = oi; }
        }
        if (tid == 0) s_tok = bi;
    }
    __syncthreads();
    int tok = s_tok;
    float valid = (s < lengths[b]) ? 1.0f : 0.0f;
    const float* we = w_emb + (long long)tok * HID;
    const float* pe = p_emb + (long long)s * HID;
    float*  zp  = g_z   + (long long)bs * HID;
    __half* zph = g_z16 + (long long)bs * HID;
    for (int h = tid; h < HID; h += blockDim.x) {
        float v = we[h] * valid + pe[h];
        zp[h]  = v;
        zph[h] = __float2half(v);
    }
}

// ---------------- residual add + LayerNorm (fp32 out + fp16 copy) ----------------
__global__ void add_ln_kernel(const float* __restrict__ a, const float* __restrict__ r,
                              const float* __restrict__ sc, const float* __restrict__ bi,
                              float* __restrict__ out, __half* __restrict__ out16) {
    int row = blockIdx.x;
    int tid = threadIdx.x;
    const float* ap = a + (long long)row * HID;
    const float* rp = r + (long long)row * HID;
    float v[4];
    float s = 0.f, sq = 0.f;
#pragma unroll
    for (int j = 0; j < 4; j++) {
        int h = tid + j*256;
        v[j] = ap[h] + rp[h];
        s  += v[j];
        sq += v[j]*v[j];
    }
    __shared__ float red1[8], red2[8];
    for (int off = 16; off > 0; off >>= 1) {
        s  += __shfl_xor_sync(0xffffffff, s,  off);
        sq += __shfl_xor_sync(0xffffffff, sq, off);
    }
    int warp = tid >> 5, lane = tid & 31;
    if (lane == 0) { red1[warp] = s; red2[warp] = sq; }
    __syncthreads();
    if (warp == 0) {
        s  = (lane < 8) ? red1[lane] : 0.f;
        sq = (lane < 8) ? red2[lane] : 0.f;
        for (int off = 4; off > 0; off >>= 1) {
            s  += __shfl_xor_sync(0xffffffff, s,  off);
            sq += __shfl_xor_sync(0xffffffff, sq, off);
        }
        if (lane == 0) { red1[0] = s; red2[0] = sq; }
    }
    __syncthreads();
    float mean = red1[0] * (1.0f / HID);
    float var  = red2[0] * (1.0f / HID) - mean * mean;
    float rstd = rsqrtf(var + 1e-5f);
    float*  op  = out   + (long long)row * HID;
    __half* oph = out16 + (long long)row * HID;
#pragma unroll
    for (int j = 0; j < 4; j++) {
        int h = tid + j*256;
        float o = (v[j] - mean) * rstd * sc[h] + bi[h];
        op[h]  = o;
        oph[h] = __float2half(o);
    }
}

// ---------------- mean-pool ----------------
__global__ void pool_kernel() {
    int b = blockIdx.y;
    int h = blockIdx.x * 256 + threadIdx.x;
    float s = 0.f;
    const float* zp = g_z + (long long)b * SEQ * HID + h;
    for (int si = 0; si < SEQ; si++)
        s += zp[(long long)si * HID];
    g_pool[b * HID + h] = s * (1.0f / SEQ);
}

// ---------------- classifier head + softmax(4) ----------------
__global__ void head_kernel(const float* __restrict__ Wfc, const float* __restrict__ bfc,
                            float* __restrict__ out) {
    int b = blockIdx.x;
    int tid = threadIdx.x;
    float p[4] = {0.f, 0.f, 0.f, 0.f};
    const float* zp = g_pool + b * HID;
    for (int h = tid; h < HID; h += 256) {
        float zv = zp[h];
#pragma unroll
        for (int c = 0; c < 4; c++) p[c] += zv * Wfc[h*4 + c];
    }
    __shared__ float red[4][256];
#pragma unroll
    for (int c = 0; c < 4; c++) red[c][tid] = p[c];
    __syncthreads();
    for (int str = 128; str > 0; str >>= 1) {
        if (tid < str)
#pragma unroll
            for (int c = 0; c < 4; c++) red[c][tid] += red[c][tid + str];
        __syncthreads();
    }
    if (tid == 0) {
        float l[4];
        float m = -1e30f;
#pragma unroll
        for (int c = 0; c < 4; c++) { l[c] = red[c][0] + bfc[c]; m = fmaxf(m, l[c]); }
        float ssum = 0.f;
#pragma unroll
        for (int c = 0; c < 4; c++) { l[c] = __expf(l[c] - m); ssum += l[c]; }
        float inv = 1.0f / ssum;
#pragma unroll
        for (int c = 0; c < 4; c++) out[b*4 + c] = l[c] * inv;
    }
}

// ---------------- host orchestration ----------------
extern "C" void kernel_launch(void* const* d_in, const int* in_sizes, int n_in,
                              void* d_out, int out_size) {
    const float* x     = (const float*)d_in[0];
    const float* w_emb = (const float*)d_in[1];
    const float* p_emb = (const float*)d_in[2];
    const float* Wq    = (const float*)d_in[3];
    const float* bq    = (const float*)d_in[4];
    const float* Wk    = (const float*)d_in[5];
    const float* bk    = (const float*)d_in[6];
    const float* Wv    = (const float*)d_in[7];
    const float* bv    = (const float*)d_in[8];
    const float* W1    = (const float*)d_in[9];
    const float* b1    = (const float*)d_in[10];
    const float* W2    = (const float*)d_in[11];
    const float* b2    = (const float*)d_in[12];
    const float* ln1_s = (const float*)d_in[13];
    const float* ln1_b = (const float*)d_in[14];
    const float* ln2_s = (const float*)d_in[15];
    const float* ln2_b = (const float*)d_in[16];
    const float* Wfc   = (const float*)d_in[17];
    const float* bfc   = (const float*)d_in[18];
    const int*   lengths = (const int*)d_in[19];
    float* out = (float*)d_out;

    float *pz, *pqkv, *patt, *pz1, *pbqkv;
    __half *pz16, *pz116, *pffh16, *pwqkv16, *pw1216;
    cudaGetSymbolAddress((void**)&pz,     g_z);
    cudaGetSymbolAddress((void**)&pz16,   g_z16);
    cudaGetSymbolAddress((void**)&pqkv,   g_qkv);
    cudaGetSymbolAddress((void**)&patt,   g_att);
    cudaGetSymbolAddress((void**)&pz1,    g_z1);
    cudaGetSymbolAddress((void**)&pz116,  g_z116);
    cudaGetSymbolAddress((void**)&pffh16, g_ffh16);
    cudaGetSymbolAddress((void**)&pwqkv16,g_wqkv16);
    cudaGetSymbolAddress((void**)&pw1216, g_w1216);
    cudaGetSymbolAddress((void**)&pbqkv,  g_bqkv);

    cudaFuncSetAttribute(gemm_h<0>, cudaFuncAttributeMaxDynamicSharedMemorySize, GEMM_SMEM);
    cudaFuncSetAttribute(gemm_h<1>, cudaFuncAttributeMaxDynamicSharedMemorySize, GEMM_SMEM);
    cudaFuncSetAttribute(flash_attn, cudaFuncAttributeMaxDynamicSharedMemorySize, FA_SMEM);

    const long long MAT = (long long)HID * HID;

    dim3 tgrid(HID/32, HID/32, NLAYER);
    dim3 tblk(32, 8);
    transpose_h_kernel<<<tgrid, tblk>>>(Wq, pwqkv16 + 0*MAT, 3*MAT);
    transpose_h_kernel<<<tgrid, tblk>>>(Wk, pwqkv16 + 1*MAT, 3*MAT);
    transpose_h_kernel<<<tgrid, tblk>>>(Wv, pwqkv16 + 2*MAT, 3*MAT);
    transpose_h_kernel<<<tgrid, tblk>>>(W1, pw1216  + 0*MAT, 2*MAT);
    transpose_h_kernel<<<tgrid, tblk>>>(W2, pw1216  + 1*MAT, 2*MAT);
    biaspack_kernel<<<(NLAYER*QKVW + 255)/256, 256>>>(bq, bk, bv);

    embed_kernel<<<BS_TOT, 256>>>(x, w_emb, p_emb, lengths);

    dim3 qkv_grid(QKVW/128, BS_TOT/128);   // (24, 60)
    dim3 ff_grid(HID/128, BS_TOT/128);     // (8, 60)

    for (int i = 0; i < NLAYER; i++) {
        long long bOff = (long long)i * HID;
        gemm_h<0><<<qkv_grid, 256, GEMM_SMEM>>>(pz16, pwqkv16 + (long long)i*3*MAT,
                                                pbqkv + (long long)i*QKVW, pqkv, QKVW);
        flash_attn<<<NB*NHEAD, FA_THREADS, FA_SMEM>>>(pqkv, lengths, patt);
        add_ln_kernel<<<BS_TOT, 256>>>(pz, patt, ln1_s + bOff, ln1_b + bOff, pz1, pz116);
        gemm_h<1><<<ff_grid, 256, GEMM_SMEM>>>(pz116, pw1216 + (long long)i*2*MAT,
                                               b1 + bOff, pffh16, HID);
        gemm_h<0><<<ff_grid, 256, GEMM_SMEM>>>(pffh16, pw1216 + (long long)i*2*MAT + MAT,
                                               b2 + bOff, patt, HID);
        add_ln_kernel<<<BS_TOT, 256>>>(pz1, patt, ln2_s + bOff, ln2_b + bOff, pz, pz16);
    }

    pool_kernel<<<dim3(HID/256, NB), 256>>>();
    head_kernel<<<NB, 256>>>(Wfc, bfc, out);
}

// round 10
// speedup vs baseline: 2.4706x; 1.1088x over previous
#include <cuda_runtime.h>
#include <cuda_fp16.h>
#include <math.h>
#include <cstdint>

#define NB     32
#define SEQ    240
#define HID    1024
#define NLAYER 8
#define NHEAD  16
#define DHEAD  64
#define NVOCAB 48
#define BS_TOT (NB*SEQ)   // 7680
#define QKVW   3072

// ---------------- device scratch (no allocation allowed) ----------------
__device__ float  g_z   [BS_TOT*HID];
__device__ __half g_z16 [BS_TOT*HID];
__device__ __half g_qkv16[(long long)BS_TOT*QKVW];
__device__ float  g_att [BS_TOT*HID];
__device__ float  g_z1  [BS_TOT*HID];
__device__ __half g_z116[BS_TOT*HID];
__device__ __half g_ffh16[BS_TOT*HID];
__device__ float  g_pool[NB*HID];
__device__ __half g_wqkv16[(long long)NLAYER*3*HID*HID];  // [L][3072][1024] transposed fp16
__device__ __half g_w1216 [(long long)NLAYER*2*HID*HID];  // [L][W1t|W2t] fp16
__device__ float  g_bqkv[NLAYER*QKVW];

// ============================ helpers ============================
__device__ __forceinline__ uint32_t smem_u32(const void* p) {
    return (uint32_t)__cvta_generic_to_shared(p);
}
__device__ __forceinline__ void cpa16(uint32_t dst, const void* src) {
    asm volatile("cp.async.cg.shared.global [%0], [%1], 16;" :: "r"(dst), "l"(src));
}
#define CPA_COMMIT() asm volatile("cp.async.commit_group;" ::: "memory")
template<int N> __device__ __forceinline__ void cpa_wait() {
    asm volatile("cp.async.wait_group %0;" :: "n"(N) : "memory");
}

__device__ __forceinline__ void mma_f16(float* c, const uint32_t* a, uint32_t b0, uint32_t b1) {
    asm volatile(
        "mma.sync.aligned.m16n8k16.row.col.f32.f16.f16.f32 "
        "{%0,%1,%2,%3}, {%4,%5,%6,%7}, {%8,%9}, {%0,%1,%2,%3};"
        : "+f"(c[0]), "+f"(c[1]), "+f"(c[2]), "+f"(c[3])
        : "r"(a[0]), "r"(a[1]), "r"(a[2]), "r"(a[3]), "r"(b0), "r"(b1));
}
__device__ __forceinline__ void ldsm_x4(uint32_t* r, uint32_t addr) {
    asm volatile("ldmatrix.sync.aligned.m8n8.x4.shared.b16 {%0,%1,%2,%3}, [%4];"
        : "=r"(r[0]), "=r"(r[1]), "=r"(r[2]), "=r"(r[3]) : "r"(addr));
}

// ============================ weight transpose -> fp16 ============================
__global__ void transpose_h_kernel(const float* __restrict__ src, __half* __restrict__ dst,
                                   long long dstZ) {
    __shared__ float t[32][33];
    long long smoff = (long long)blockIdx.z * HID * HID;
    long long dmoff = (long long)blockIdx.z * dstZ;
    int x0 = blockIdx.x * 32, y0 = blockIdx.y * 32;
    int tx = threadIdx.x, ty = threadIdx.y;  // 32 x 8
#pragma unroll
    for (int j = 0; j < 32; j += 8)
        t[ty + j][tx] = src[smoff + (long long)(y0 + ty + j) * HID + x0 + tx];
    __syncthreads();
#pragma unroll
    for (int j = 0; j < 32; j += 8)
        dst[dmoff + (long long)(x0 + ty + j) * HID + y0 + tx] = __float2half(t[tx][ty + j]);
}

// bias pack: g_bqkv[l][t*1024+n]
__global__ void biaspack_kernel(const float* __restrict__ bq, const float* __restrict__ bk,
                                const float* __restrict__ bv) {
    int idx = blockIdx.x * 256 + threadIdx.x;
    if (idx >= NLAYER * QKVW) return;
    int l = idx / QKVW, r = idx % QKVW;
    int t = r >> 10, n = r & 1023;
    const float* src = (t == 0) ? bq : (t == 1) ? bk : bv;
    g_bqkv[idx] = src[l * HID + n];
}

// ============================ fp16 mma.sync GEMM (ldmatrix fragments) ============================
// C[M,N] = A[M,K] @ Wt^T + bias ; A fp16 [M,K] (lda=HID), Wt fp16 [N,K].
// BM=128, BN=128, BK=32 halves; 256 threads; warp grid 4x2, warp tile 32x64.
#define BKC   32
#define PADH  40
#define ABYTES (128 * PADH * 2)          // 10240
#define STAGEB (2 * ABYTES)              // 20480
#define NSTAGE 3
#define GEMM_SMEM (NSTAGE * STAGEB)      // 61440

__device__ __forceinline__ void gemm_load_stage(uint32_t sbase, int s, int kc, int tid,
                                                const __half* __restrict__ A,
                                                const __half* __restrict__ Bw,
                                                int row0, int col0) {
    uint32_t abase = sbase + s * STAGEB;
    uint32_t bbase = abase + ABYTES;
    const __half* Ag = A  + (long long)row0 * HID + kc * BKC;
    const __half* Bg = Bw + (long long)col0 * HID + kc * BKC;
#pragma unroll
    for (int j = 0; j < 2; j++) {
        int c = tid + j * 256;
        int r = c >> 2, q = c & 3;
        uint32_t so = (uint32_t)(r * PADH + q * 8) * 2;
        cpa16(abase + so, Ag + (long long)r * HID + q * 8);
        cpa16(bbase + so, Bg + (long long)r * HID + q * 8);
    }
}

// ACT: GELU on output ; OUT16: write __half instead of float
template<int ACT, int OUT16>
__global__ __launch_bounds__(256, 2)
void gemm_h(const __half* __restrict__ A, const __half* __restrict__ Bw,
            const float* __restrict__ bias, void* __restrict__ Cv, int ldC) {
    extern __shared__ __half smem[];
    const int tid = threadIdx.x;
    const int wid = tid >> 5, lane = tid & 31;
    const int wm = wid & 3, wn = wid >> 2;
    const int grp = lane >> 2, qid = lane & 3;
    const int row0 = blockIdx.y * 128;
    const int col0 = blockIdx.x * 128;
    uint32_t sbase = smem_u32(smem);

    float acc[2][8][4];
#pragma unroll
    for (int mf = 0; mf < 2; mf++)
#pragma unroll
        for (int nf = 0; nf < 8; nf++)
#pragma unroll
            for (int i = 0; i < 4; i++) acc[mf][nf][i] = 0.f;

    const int NKC = HID / BKC;   // 32

    gemm_load_stage(sbase, 0, 0, tid, A, Bw, row0, col0);
    CPA_COMMIT();
    gemm_load_stage(sbase, 1, 1, tid, A, Bw, row0, col0);
    CPA_COMMIT();

    // lane-dependent ldmatrix address components
    const int a_row = wm * 32 + (lane & 15);     // + mf*16
    const int a_k   = (lane >> 4) * 8;           // + kk*16
    const int b_row = wn * 64 + (lane & 7);      // + nf*8
    const int b_k   = (lane >> 3) * 8;           // covers k0..31 via x4

    for (int kc = 0; kc < NKC; kc++) {
        int s = kc % NSTAGE;
        if (kc + 2 < NKC)
            gemm_load_stage(sbase, (kc + 2) % NSTAGE, kc + 2, tid, A, Bw, row0, col0);
        CPA_COMMIT();
        cpa_wait<2>();
        __syncthreads();

        uint32_t sAu = sbase + s * STAGEB;
        uint32_t sBu = sAu + ABYTES;

        uint32_t afr[2][2][4];
#pragma unroll
        for (int mf = 0; mf < 2; mf++)
#pragma unroll
            for (int kk = 0; kk < 2; kk++)
                ldsm_x4(afr[mf][kk],
                        sAu + (uint32_t)((a_row + mf * 16) * PADH + kk * 16 + a_k) * 2);

#pragma unroll
        for (int nf = 0; nf < 8; nf++) {
            uint32_t bfr[4];
            ldsm_x4(bfr, sBu + (uint32_t)((b_row + nf * 8) * PADH + b_k) * 2);
            mma_f16(acc[0][nf], afr[0][0], bfr[0], bfr[1]);
            mma_f16(acc[1][nf], afr[1][0], bfr[0], bfr[1]);
            mma_f16(acc[0][nf], afr[0][1], bfr[2], bfr[3]);
            mma_f16(acc[1][nf], afr[1][1], bfr[2], bfr[3]);
        }
        __syncthreads();
    }

#pragma unroll
    for (int mf = 0; mf < 2; mf++) {
        int r0 = row0 + wm * 32 + mf * 16 + grp;
#pragma unroll
        for (int nf = 0; nf < 8; nf++) {
            int cg = col0 + wn * 64 + nf * 8 + 2 * qid;
            float bv0 = bias[cg], bv1 = bias[cg + 1];
            float v00 = acc[mf][nf][0] + bv0;
            float v01 = acc[mf][nf][1] + bv1;
            float v10 = acc[mf][nf][2] + bv0;
            float v11 = acc[mf][nf][3] + bv1;
            if (ACT) {
                v00 = 0.5f * v00 * (1.0f + erff(v00 * 0.70710678118654752f));
                v01 = 0.5f * v01 * (1.0f + erff(v01 * 0.70710678118654752f));
                v10 = 0.5f * v10 * (1.0f + erff(v10 * 0.70710678118654752f));
                v11 = 0.5f * v11 * (1.0f + erff(v11 * 0.70710678118654752f));
            }
            if (OUT16) {
                __half* C = (__half*)Cv;
                *(__half2*)&C[(long long)r0 * ldC + cg]       = __floats2half2_rn(v00, v01);
                *(__half2*)&C[(long long)(r0 + 8) * ldC + cg] = __floats2half2_rn(v10, v11);
            } else {
                float* C = (float*)Cv;
                *(float2*)&C[(long long)r0 * ldC + cg]       = make_float2(v00, v01);
                *(float2*)&C[(long long)(r0 + 8) * ldC + cg] = make_float2(v10, v11);
            }
        }
    }
}

// ============================ fused flash attention (fp32 compute, fp16 input) ============================
#define FA_THREADS 512
#define KS_STRIDE  68
#define VT_STRIDE  244
#define FA_KS_FL   (240 * KS_STRIDE)
#define FA_VT_FL   (64 * VT_STRIDE)
#define FA_QS_FL   (16 * 4 * KS_STRIDE)
#define FA_PS_FL   (16 * 4 * 240)
#define FA_SMEM    ((FA_KS_FL + FA_VT_FL + FA_QS_FL + FA_PS_FL) * 4)

__global__ __launch_bounds__(FA_THREADS, 1)
void flash_attn(const __half* __restrict__ qkv, const int* __restrict__ lengths,
                float* __restrict__ att) {
    extern __shared__ float fs[];
    float* Ks = fs;
    float* Vt = Ks + FA_KS_FL;
    float* Qs = Vt + FA_VT_FL;
    float* Ps = Qs + FA_QS_FL;

    const int bh = blockIdx.x;
    const int b = bh >> 4, h = bh & 15;
    const int tid = threadIdx.x;
    const int w = tid >> 5, lane = tid & 31;
    const int len = lengths[b];
    const __half* base = qkv + (long long)b * SEQ * QKVW + h * DHEAD;
    const float scale = 1.0f / 32.0f;

    // stage K (row-major fp32) and V (transposed fp32) from fp16 gmem
    for (int i = tid; i < 240 * 8; i += FA_THREADS) {
        int s = i >> 3, c = i & 7;
        uint4 kraw = *(const uint4*)(base + (long long)s * QKVW + 1024 + c * 8);
        uint4 vraw = *(const uint4*)(base + (long long)s * QKVW + 2048 + c * 8);
        const __half2* kh = (const __half2*)&kraw;
        const __half2* vh = (const __half2*)&vraw;
        int d0 = c * 8;
#pragma unroll
        for (int j = 0; j < 4; j++) {
            float2 kf = __half22float2(kh[j]);
            float2 vf = __half22float2(vh[j]);
            Ks[s * KS_STRIDE + d0 + 2*j]     = kf.x;
            Ks[s * KS_STRIDE + d0 + 2*j + 1] = kf.y;
            Vt[(d0 + 2*j) * VT_STRIDE + s]     = vf.x;
            Vt[(d0 + 2*j + 1) * VT_STRIDE + s] = vf.y;
        }
    }
    __syncthreads();

    float* Qw = Qs + w * (4 * KS_STRIDE);
    float* Pw = Ps + w * (4 * 240);

    for (int grp = w; grp < 60; grp += 16) {
        const int q0 = grp * 4;
        const int jmax = (q0 + 3) >> 5;

        {   // stage 4 Q rows: lane covers (row = lane>>3, chunk = lane&7)
            int r = lane >> 3, c = lane & 7;
            uint4 qraw = *(const uint4*)(base + (long long)(q0 + r) * QKVW + c * 8);
            const __half2* qh = (const __half2*)&qraw;
#pragma unroll
            for (int j = 0; j < 4; j++) {
                float2 qf = __half22float2(qh[j]);
                Qw[r * KS_STRIDE + c * 8 + 2*j]     = qf.x;
                Qw[r * KS_STRIDE + c * 8 + 2*j + 1] = qf.y;
            }
        }
        __syncwarp();

        float sc[4][8];
#pragma unroll
        for (int r = 0; r < 4; r++)
#pragma unroll
            for (int j = 0; j < 8; j++) sc[r][j] = 0.f;

#pragma unroll
        for (int d4 = 0; d4 < 16; d4++) {
            float4 qa = *(float4*)&Qw[0 * KS_STRIDE + d4 * 4];
            float4 qb = *(float4*)&Qw[1 * KS_STRIDE + d4 * 4];
            float4 qc = *(float4*)&Qw[2 * KS_STRIDE + d4 * 4];
            float4 qd = *(float4*)&Qw[3 * KS_STRIDE + d4 * 4];
            for (int j = 0; j <= jmax; j++) {
                int k = lane + 32 * j;
                float4 kk = *(float4*)&Ks[k * KS_STRIDE + d4 * 4];
                sc[0][j] += qa.x*kk.x + qa.y*kk.y + qa.z*kk.z + qa.w*kk.w;
                sc[1][j] += qb.x*kk.x + qb.y*kk.y + qb.z*kk.z + qb.w*kk.w;
                sc[2][j] += qc.x*kk.x + qc.y*kk.y + qc.z*kk.z + qc.w*kk.w;
                sc[3][j] += qd.x*kk.x + qd.y*kk.y + qd.z*kk.z + qd.w*kk.w;
            }
        }

#pragma unroll
        for (int r = 0; r < 4; r++) {
            int qr = q0 + r;
            float v[8];
            float m = -1e30f;
#pragma unroll
            for (int j = 0; j < 8; j++) {
                int k = lane + 32 * j;
                v[j] = (k <= qr) ? sc[r][j] * scale : -1e30f;
                m = fmaxf(m, v[j]);
            }
#pragma unroll
            for (int off = 16; off > 0; off >>= 1)
                m = fmaxf(m, __shfl_xor_sync(0xffffffff, m, off));
            float ssum = 0.f;
#pragma unroll
            for (int j = 0; j < 8; j++) {
                v[j] = __expf(v[j] - m);
                ssum += v[j];
            }
#pragma unroll
            for (int off = 16; off > 0; off >>= 1)
                ssum += __shfl_xor_sync(0xffffffff, ssum, off);
            float inv = (qr < len) ? (1.0f / ssum) : 0.0f;
#pragma unroll
            for (int j = 0; j < 8; j++) {
                int k = lane + 32 * j;
                if (k < 240) Pw[r * 240 + k] = v[j] * inv;
            }
        }
        __syncwarp();

        float a00 = 0.f, a01 = 0.f, a10 = 0.f, a11 = 0.f;
        float a20 = 0.f, a21 = 0.f, a30 = 0.f, a31 = 0.f;
        const float4* V0 = (const float4*)&Vt[lane * VT_STRIDE];
        const float4* V1 = (const float4*)&Vt[(lane + 32) * VT_STRIDE];
        const float4* P0 = (const float4*)&Pw[0];
        const float4* P1 = (const float4*)&Pw[240];
        const float4* P2 = (const float4*)&Pw[480];
        const float4* P3 = (const float4*)&Pw[720];
        for (int k4 = 0; k4 <= grp; k4++) {
            float4 v0 = V0[k4], v1 = V1[k4];
            float4 p0 = P0[k4], p1 = P1[k4], p2 = P2[k4], p3 = P3[k4];
            a00 += p0.x*v0.x + p0.y*v0.y + p0.z*v0.z + p0.w*v0.w;
            a01 += p0.x*v1.x + p0.y*v1.y + p0.z*v1.z + p0.w*v1.w;
            a10 += p1.x*v0.x + p1.y*v0.y + p1.z*v0.z + p1.w*v0.w;
            a11 += p1.x*v1.x + p1.y*v1.y + p1.z*v1.z + p1.w*v1.w;
            a20 += p2.x*v0.x + p2.y*v0.y + p2.z*v0.z + p2.w*v0.w;
            a21 += p2.x*v1.x + p2.y*v1.y + p2.z*v1.z + p2.w*v1.w;
            a30 += p3.x*v0.x + p3.y*v0.y + p3.z*v0.z + p3.w*v0.w;
            a31 += p3.x*v1.x + p3.y*v1.y + p3.z*v1.z + p3.w*v1.w;
        }
        float* ob = att + (long long)(b * SEQ + q0) * HID + h * DHEAD;
        ob[0 * HID + lane] = a00;  ob[0 * HID + lane + 32] = a01;
        ob[1 * HID + lane] = a10;  ob[1 * HID + lane + 32] = a11;
        ob[2 * HID + lane] = a20;  ob[2 * HID + lane + 32] = a21;
        ob[3 * HID + lane] = a30;  ob[3 * HID + lane + 32] = a31;
        __syncwarp();
    }
}

// ---------------- embedding: argmax + gather + posenc (fp32 + fp16 copy) ----------------
__global__ void embed_kernel(const float* __restrict__ x,
                             const float* __restrict__ w_emb,
                             const float* __restrict__ p_emb,
                             const int*   __restrict__ lengths) {
    int bs = blockIdx.x;
    int b = bs / SEQ, s = bs % SEQ;
    __shared__ int s_tok;
    int tid = threadIdx.x;
    if (tid < 32) {
        const float* xp = x + (long long)bs * NVOCAB;
        float bv = -1e30f; int bi = 0;
        for (int c = tid; c < NVOCAB; c += 32) {
            float v = xp[c];
            if (v > bv) { bv = v; bi = c; }
        }
        for (int off = 16; off > 0; off >>= 1) {
            float ov = __shfl_down_sync(0xffffffff, bv, off);
            int   oi = __shfl_down_sync(0xffffffff, bi, off);
            if (ov > bv || (ov == bv && oi < bi)) { bv = ov; bi = oi; }
        }
        if (tid == 0) s_tok = bi;
    }
    __syncthreads();
    int tok = s_tok;
    float valid = (s < lengths[b]) ? 1.0f : 0.0f;
    const float* we = w_emb + (long long)tok * HID;
    const float* pe = p_emb + (long long)s * HID;
    float*  zp  = g_z   + (long long)bs * HID;
    __half* zph = g_z16 + (long long)bs * HID;
    for (int h = tid; h < HID; h += blockDim.x) {
        float v = we[h] * valid + pe[h];
        zp[h]  = v;
        zph[h] = __float2half(v);
    }
}

// ---------------- residual add + LayerNorm (fp32 out + fp16 copy) ----------------
__global__ void add_ln_kernel(const float* __restrict__ a, const float* __restrict__ r,
                              const float* __restrict__ sc, const float* __restrict__ bi,
                              float* __restrict__ out, __half* __restrict__ out16) {
    int row = blockIdx.x;
    int tid = threadIdx.x;
    const float* ap = a + (long long)row * HID;
    const float* rp = r + (long long)row * HID;
    float v[4];
    float s = 0.f, sq = 0.f;
#pragma unroll
    for (int j = 0; j < 4; j++) {
        int h = tid + j*256;
        v[j] = ap[h] + rp[h];
        s  += v[j];
        sq += v[j]*v[j];
    }
    __shared__ float red1[8], red2[8];
    for (int off = 16; off > 0; off >>= 1) {
        s  += __shfl_xor_sync(0xffffffff, s,  off);
        sq += __shfl_xor_sync(0xffffffff, sq, off);
    }
    int warp = tid >> 5, lane = tid & 31;
    if (lane == 0) { red1[warp] = s; red2[warp] = sq; }
    __syncthreads();
    if (warp == 0) {
        s  = (lane < 8) ? red1[lane] : 0.f;
        sq = (lane < 8) ? red2[lane] : 0.f;
        for (int off = 4; off > 0; off >>= 1) {
            s  += __shfl_xor_sync(0xffffffff, s,  off);
            sq += __shfl_xor_sync(0xffffffff, sq, off);
        }
        if (lane == 0) { red1[0] = s; red2[0] = sq; }
    }
    __syncthreads();
    float mean = red1[0] * (1.0f / HID);
    float var  = red2[0] * (1.0f / HID) - mean * mean;
    float rstd = rsqrtf(var + 1e-5f);
    float*  op  = out   + (long long)row * HID;
    __half* oph = out16 + (long long)row * HID;
#pragma unroll
    for (int j = 0; j < 4; j++) {
        int h = tid + j*256;
        float o = (v[j] - mean) * rstd * sc[h] + bi[h];
        op[h]  = o;
        oph[h] = __float2half(o);
    }
}

// ---------------- mean-pool ----------------
__global__ void pool_kernel() {
    int b = blockIdx.y;
    int h = blockIdx.x * 256 + threadIdx.x;
    float s = 0.f;
    const float* zp = g_z + (long long)b * SEQ * HID + h;
    for (int si = 0; si < SEQ; si++)
        s += zp[(long long)si * HID];
    g_pool[b * HID + h] = s * (1.0f / SEQ);
}

// ---------------- classifier head + softmax(4) ----------------
__global__ void head_kernel(const float* __restrict__ Wfc, const float* __restrict__ bfc,
                            float* __restrict__ out) {
    int b = blockIdx.x;
    int tid = threadIdx.x;
    float p[4] = {0.f, 0.f, 0.f, 0.f};
    const float* zp = g_pool + b * HID;
    for (int h = tid; h < HID; h += 256) {
        float zv = zp[h];
#pragma unroll
        for (int c = 0; c < 4; c++) p[c] += zv * Wfc[h*4 + c];
    }
    __shared__ float red[4][256];
#pragma unroll
    for (int c = 0; c < 4; c++) red[c][tid] = p[c];
    __syncthreads();
    for (int str = 128; str > 0; str >>= 1) {
        if (tid < str)
#pragma unroll
            for (int c = 0; c < 4; c++) red[c][tid] += red[c][tid + str];
        __syncthreads();
    }
    if (tid == 0) {
        float l[4];
        float m = -1e30f;
#pragma unroll
        for (int c = 0; c < 4; c++) { l[c] = red[c][0] + bfc[c]; m = fmaxf(m, l[c]); }
        float ssum = 0.f;
#pragma unroll
        for (int c = 0; c < 4; c++) { l[c] = __expf(l[c] - m); ssum += l[c]; }
        float inv = 1.0f / ssum;
#pragma unroll
        for (int c = 0; c < 4; c++) out[b*4 + c] = l[c] * inv;
    }
}

// ---------------- host orchestration ----------------
extern "C" void kernel_launch(void* const* d_in, const int* in_sizes, int n_in,
                              void* d_out, int out_size) {
    const float* x     = (const float*)d_in[0];
    const float* w_emb = (const float*)d_in[1];
    const float* p_emb = (const float*)d_in[2];
    const float* Wq    = (const float*)d_in[3];
    const float* bq    = (const float*)d_in[4];
    const float* Wk    = (const float*)d_in[5];
    const float* bk    = (const float*)d_in[6];
    const float* Wv    = (const float*)d_in[7];
    const float* bv    = (const float*)d_in[8];
    const float* W1    = (const float*)d_in[9];
    const float* b1    = (const float*)d_in[10];
    const float* W2    = (const float*)d_in[11];
    const float* b2    = (const float*)d_in[12];
    const float* ln1_s = (const float*)d_in[13];
    const float* ln1_b = (const float*)d_in[14];
    const float* ln2_s = (const float*)d_in[15];
    const float* ln2_b = (const float*)d_in[16];
    const float* Wfc   = (const float*)d_in[17];
    const float* bfc   = (const float*)d_in[18];
    const int*   lengths = (const int*)d_in[19];
    float* out = (float*)d_out;

    float *pz, *patt, *pz1, *pbqkv;
    __half *pz16, *pz116, *pffh16, *pwqkv16, *pw1216, *pqkv16;
    cudaGetSymbolAddress((void**)&pz,     g_z);
    cudaGetSymbolAddress((void**)&pz16,   g_z16);
    cudaGetSymbolAddress((void**)&pqkv16, g_qkv16);
    cudaGetSymbolAddress((void**)&patt,   g_att);
    cudaGetSymbolAddress((void**)&pz1,    g_z1);
    cudaGetSymbolAddress((void**)&pz116,  g_z116);
    cudaGetSymbolAddress((void**)&pffh16, g_ffh16);
    cudaGetSymbolAddress((void**)&pwqkv16,g_wqkv16);
    cudaGetSymbolAddress((void**)&pw1216, g_w1216);
    cudaGetSymbolAddress((void**)&pbqkv,  g_bqkv);

    cudaFuncSetAttribute((const void*)gemm_h<0,0>, cudaFuncAttributeMaxDynamicSharedMemorySize, GEMM_SMEM);
    cudaFuncSetAttribute((const void*)gemm_h<0,1>, cudaFuncAttributeMaxDynamicSharedMemorySize, GEMM_SMEM);
    cudaFuncSetAttribute((const void*)gemm_h<1,1>, cudaFuncAttributeMaxDynamicSharedMemorySize, GEMM_SMEM);
    cudaFuncSetAttribute((const void*)flash_attn, cudaFuncAttributeMaxDynamicSharedMemorySize, FA_SMEM);

    const long long MAT = (long long)HID * HID;

    dim3 tgrid(HID/32, HID/32, NLAYER);
    dim3 tblk(32, 8);
    transpose_h_kernel<<<tgrid, tblk>>>(Wq, pwqkv16 + 0*MAT, 3*MAT);
    transpose_h_kernel<<<tgrid, tblk>>>(Wk, pwqkv16 + 1*MAT, 3*MAT);
    transpose_h_kernel<<<tgrid, tblk>>>(Wv, pwqkv16 + 2*MAT, 3*MAT);
    transpose_h_kernel<<<tgrid, tblk>>>(W1, pw1216  + 0*MAT, 2*MAT);
    transpose_h_kernel<<<tgrid, tblk>>>(W2, pw1216  + 1*MAT, 2*MAT);
    biaspack_kernel<<<(NLAYER*QKVW + 255)/256, 256>>>(bq, bk, bv);

    embed_kernel<<<BS_TOT, 256>>>(x, w_emb, p_emb, lengths);

    dim3 qkv_grid(QKVW/128, BS_TOT/128);   // (24, 60)
    dim3 ff_grid(HID/128, BS_TOT/128);     // (8, 60)

    for (int i = 0; i < NLAYER; i++) {
        long long bOff = (long long)i * HID;
        gemm_h<0,1><<<qkv_grid, 256, GEMM_SMEM>>>(pz16, pwqkv16 + (long long)i*3*MAT,
                                                  pbqkv + (long long)i*QKVW, pqkv16, QKVW);
        flash_attn<<<NB*NHEAD, FA_THREADS, FA_SMEM>>>(pqkv16, lengths, patt);
        add_ln_kernel<<<BS_TOT, 256>>>(pz, patt, ln1_s + bOff, ln1_b + bOff, pz1, pz116);
        gemm_h<1,1><<<ff_grid, 256, GEMM_SMEM>>>(pz116, pw1216 + (long long)i*2*MAT,
                                                 b1 + bOff, pffh16, HID);
        gemm_h<0,0><<<ff_grid, 256, GEMM_SMEM>>>(pffh16, pw1216 + (long long)i*2*MAT + MAT,
                                                 b2 + bOff, patt, HID);
        add_ln_kernel<<<BS_TOT, 256>>>(pz1, patt, ln2_s + bOff, ln2_b + bOff, pz, pz16);
    }

    pool_kernel<<<dim3(HID/256, NB), 256>>>();
    head_kernel<<<NB, 256>>>(Wfc, bfc, out);
}

// round 12
// speedup vs baseline: 3.3813x; 1.3686x over previous
#include <cuda_runtime.h>
#include <cuda_fp16.h>
#include <math.h>
#include <cstdint>

#define NB     32
#define SEQ    240
#define HID    1024
#define NLAYER 8
#define NHEAD  16
#define DHEAD  64
#define NVOCAB 48
#define BS_TOT (NB*SEQ)   // 7680
#define QKVW   3072

// ---------------- device scratch (no allocation allowed) ----------------
__device__ float  g_z   [BS_TOT*HID];
__device__ __half g_z16 [BS_TOT*HID];
__device__ __half g_qkv16[(long long)BS_TOT*QKVW];
__device__ float  g_att [BS_TOT*HID];
__device__ float  g_z1  [BS_TOT*HID];
__device__ __half g_z116[BS_TOT*HID];
__device__ __half g_ffh16[BS_TOT*HID];
__device__ float  g_pool[NB*HID];
__device__ __half g_wqkv16[(long long)NLAYER*3*HID*HID];  // [L][3072][1024] transposed fp16
__device__ __half g_w1216 [(long long)NLAYER*2*HID*HID];  // [L][W1t|W2t] fp16
__device__ float  g_bqkv[NLAYER*QKVW];

// ============================ helpers ============================
__device__ __forceinline__ uint32_t smem_u32(const void* p) {
    return (uint32_t)__cvta_generic_to_shared(p);
}
__device__ __forceinline__ void cpa16(uint32_t dst, const void* src) {
    asm volatile("cp.async.cg.shared.global [%0], [%1], 16;" :: "r"(dst), "l"(src));
}
#define CPA_COMMIT() asm volatile("cp.async.commit_group;" ::: "memory")
template<int N> __device__ __forceinline__ void cpa_wait() {
    asm volatile("cp.async.wait_group %0;" :: "n"(N) : "memory");
}

__device__ __forceinline__ void mma_f16(float* c, const uint32_t* a, uint32_t b0, uint32_t b1) {
    asm volatile(
        "mma.sync.aligned.m16n8k16.row.col.f32.f16.f16.f32 "
        "{%0,%1,%2,%3}, {%4,%5,%6,%7}, {%8,%9}, {%0,%1,%2,%3};"
        : "+f"(c[0]), "+f"(c[1]), "+f"(c[2]), "+f"(c[3])
        : "r"(a[0]), "r"(a[1]), "r"(a[2]), "r"(a[3]), "r"(b0), "r"(b1));
}
__device__ __forceinline__ void ldsm_x4(uint32_t* r, uint32_t addr) {
    asm volatile("ldmatrix.sync.aligned.m8n8.x4.shared.b16 {%0,%1,%2,%3}, [%4];"
        : "=r"(r[0]), "=r"(r[1]), "=r"(r[2]), "=r"(r[3]) : "r"(addr));
}
__device__ __forceinline__ void ldsm_x4_t(uint32_t* r, uint32_t addr) {
    asm volatile("ldmatrix.sync.aligned.m8n8.x4.trans.shared.b16 {%0,%1,%2,%3}, [%4];"
        : "=r"(r[0]), "=r"(r[1]), "=r"(r[2]), "=r"(r[3]) : "r"(addr));
}

// ============================ weight transpose -> fp16 ============================
__global__ void transpose_h_kernel(const float* __restrict__ src, __half* __restrict__ dst,
                                   long long dstZ) {
    __shared__ float t[32][33];
    long long smoff = (long long)blockIdx.z * HID * HID;
    long long dmoff = (long long)blockIdx.z * dstZ;
    int x0 = blockIdx.x * 32, y0 = blockIdx.y * 32;
    int tx = threadIdx.x, ty = threadIdx.y;  // 32 x 8
#pragma unroll
    for (int j = 0; j < 32; j += 8)
        t[ty + j][tx] = src[smoff + (long long)(y0 + ty + j) * HID + x0 + tx];
    __syncthreads();
#pragma unroll
    for (int j = 0; j < 32; j += 8)
        dst[dmoff + (long long)(x0 + ty + j) * HID + y0 + tx] = __float2half(t[tx][ty + j]);
}

// bias pack: g_bqkv[l][t*1024+n]
__global__ void biaspack_kernel(const float* __restrict__ bq, const float* __restrict__ bk,
                                const float* __restrict__ bv) {
    int idx = blockIdx.x * 256 + threadIdx.x;
    if (idx >= NLAYER * QKVW) return;
    int l = idx / QKVW, r = idx % QKVW;
    int t = r >> 10, n = r & 1023;
    const float* src = (t == 0) ? bq : (t == 1) ? bk : bv;
    g_bqkv[idx] = src[l * HID + n];
}

// ============================ fp16 mma.sync GEMM (ldmatrix fragments) ============================
#define BKC   32
#define PADH  40
#define ABYTES (128 * PADH * 2)          // 10240
#define STAGEB (2 * ABYTES)              // 20480
#define NSTAGE 3
#define GEMM_SMEM (NSTAGE * STAGEB)      // 61440

__device__ __forceinline__ void gemm_load_stage(uint32_t sbase, int s, int kc, int tid,
                                                const __half* __restrict__ A,
                                                const __half* __restrict__ Bw,
                                                int row0, int col0) {
    uint32_t abase = sbase + s * STAGEB;
    uint32_t bbase = abase + ABYTES;
    const __half* Ag = A  + (long long)row0 * HID + kc * BKC;
    const __half* Bg = Bw + (long long)col0 * HID + kc * BKC;
#pragma unroll
    for (int j = 0; j < 2; j++) {
        int c = tid + j * 256;
        int r = c >> 2, q = c & 3;
        uint32_t so = (uint32_t)(r * PADH + q * 8) * 2;
        cpa16(abase + so, Ag + (long long)r * HID + q * 8);
        cpa16(bbase + so, Bg + (long long)r * HID + q * 8);
    }
}

// ACT: GELU on output ; OUT16: write __half instead of float
template<int ACT, int OUT16>
__global__ __launch_bounds__(256, 2)
void gemm_h(const __half* __restrict__ A, const __half* __restrict__ Bw,
            const float* __restrict__ bias, void* __restrict__ Cv, int ldC) {
    extern __shared__ __half smem[];
    const int tid = threadIdx.x;
    const int wid = tid >> 5, lane = tid & 31;
    const int wm = wid & 3, wn = wid >> 2;
    const int grp = lane >> 2, qid = lane & 3;
    const int row0 = blockIdx.y * 128;
    const int col0 = blockIdx.x * 128;
    uint32_t sbase = smem_u32(smem);

    float acc[2][8][4];
#pragma unroll
    for (int mf = 0; mf < 2; mf++)
#pragma unroll
        for (int nf = 0; nf < 8; nf++)
#pragma unroll
            for (int i = 0; i < 4; i++) acc[mf][nf][i] = 0.f;

    const int NKC = HID / BKC;   // 32

    gemm_load_stage(sbase, 0, 0, tid, A, Bw, row0, col0);
    CPA_COMMIT();
    gemm_load_stage(sbase, 1, 1, tid, A, Bw, row0, col0);
    CPA_COMMIT();

    const int a_row = wm * 32 + (lane & 15);
    const int a_k   = (lane >> 4) * 8;
    const int b_row = wn * 64 + (lane & 7);
    const int b_k   = (lane >> 3) * 8;

    for (int kc = 0; kc < NKC; kc++) {
        int s = kc % NSTAGE;
        if (kc + 2 < NKC)
            gemm_load_stage(sbase, (kc + 2) % NSTAGE, kc + 2, tid, A, Bw, row0, col0);
        CPA_COMMIT();
        cpa_wait<2>();
        __syncthreads();

        uint32_t sAu = sbase + s * STAGEB;
        uint32_t sBu = sAu + ABYTES;

        uint32_t afr[2][2][4];
#pragma unroll
        for (int mf = 0; mf < 2; mf++)
#pragma unroll
            for (int kk = 0; kk < 2; kk++)
                ldsm_x4(afr[mf][kk],
                        sAu + (uint32_t)((a_row + mf * 16) * PADH + kk * 16 + a_k) * 2);

#pragma unroll
        for (int nf = 0; nf < 8; nf++) {
            uint32_t bfr[4];
            ldsm_x4(bfr, sBu + (uint32_t)((b_row + nf * 8) * PADH + b_k) * 2);
            mma_f16(acc[0][nf], afr[0][0], bfr[0], bfr[1]);
            mma_f16(acc[1][nf], afr[1][0], bfr[0], bfr[1]);
            mma_f16(acc[0][nf], afr[0][1], bfr[2], bfr[3]);
            mma_f16(acc[1][nf], afr[1][1], bfr[2], bfr[3]);
        }
        __syncthreads();
    }

#pragma unroll
    for (int mf = 0; mf < 2; mf++) {
        int r0 = row0 + wm * 32 + mf * 16 + grp;
#pragma unroll
        for (int nf = 0; nf < 8; nf++) {
            int cg = col0 + wn * 64 + nf * 8 + 2 * qid;
            float bv0 = bias[cg], bv1 = bias[cg + 1];
            float v00 = acc[mf][nf][0] + bv0;
            float v01 = acc[mf][nf][1] + bv1;
            float v10 = acc[mf][nf][2] + bv0;
            float v11 = acc[mf][nf][3] + bv1;
            if (ACT) {
                v00 = 0.5f * v00 * (1.0f + erff(v00 * 0.70710678118654752f));
                v01 = 0.5f * v01 * (1.0f + erff(v01 * 0.70710678118654752f));
                v10 = 0.5f * v10 * (1.0f + erff(v10 * 0.70710678118654752f));
                v11 = 0.5f * v11 * (1.0f + erff(v11 * 0.70710678118654752f));
            }
            if (OUT16) {
                __half* C = (__half*)Cv;
                *(__half2*)&C[(long long)r0 * ldC + cg]       = __floats2half2_rn(v00, v01);
                *(__half2*)&C[(long long)(r0 + 8) * ldC + cg] = __floats2half2_rn(v10, v11);
            } else {
                float* C = (float*)Cv;
                *(float2*)&C[(long long)r0 * ldC + cg]       = make_float2(v00, v01);
                *(float2*)&C[(long long)(r0 + 8) * ldC + cg] = make_float2(v10, v11);
            }
        }
    }
}

// ============================ tensor-core flash attention (flash-v2) ============================
// Block: 256 thr / 8 warps; grid (NB*NHEAD, 2). Block = (b,h,half): q rows half*128..+127.
// Warp w: 16 q rows. Online softmax; S/P in registers; P reused as MMA A-operand.
#define PADH2   72                          // halves per smem row (144B)
#define QH_OFF  0
#define KH_OFF  (128 * PADH2 * 2)           // 18432
#define VH_OFF  (KH_OFF + 240 * PADH2 * 2)  // 52992
#define FA2_SMEM (VH_OFF + 240 * PADH2 * 2) // 87552

__global__ __launch_bounds__(256, 2)
void flash_attn2(const __half* __restrict__ qkv, const int* __restrict__ lengths,
                 float* __restrict__ att) {
    extern __shared__ char fsm[];
    const int bh = blockIdx.x;
    const int half = blockIdx.y;
    const int b = bh >> 4, h = bh & 15;
    const int tid = threadIdx.x;
    const int w = tid >> 5, lane = tid & 31;
    const int grp = lane >> 2, qid = lane & 3;
    const int rbase = half * 128;
    const int len = lengths[b];
    const int kneed = half ? 240 : 128;      // K/V rows needed (causal)

    const __half* base = qkv + (long long)b * SEQ * QKVW + h * DHEAD;

    // ---- stage Q (own 128 rows), K, V (kneed rows) as fp16 [row][PADH2] ----
    {
        const int nQ = 128 * 8, nK = kneed * 8;
        for (int i = tid; i < nQ + 2 * nK; i += 256) {
            uint4 val = make_uint4(0, 0, 0, 0);
            char* dst;
            if (i < nQ) {
                int r = i >> 3, c = i & 7;
                int s = rbase + r;
                if (s < SEQ) val = *(const uint4*)(base + (long long)s * QKVW + c * 8);
                dst = fsm + QH_OFF + (r * PADH2 + c * 8) * 2;
            } else if (i < nQ + nK) {
                int j = i - nQ; int r = j >> 3, c = j & 7;
                val = *(const uint4*)(base + (long long)r * QKVW + 1024 + c * 8);
                dst = fsm + KH_OFF + (r * PADH2 + c * 8) * 2;
            } else {
                int j = i - nQ - nK; int r = j >> 3, c = j & 7;
                val = *(const uint4*)(base + (long long)r * QKVW + 2048 + c * 8);
                dst = fsm + VH_OFF + (r * PADH2 + c * 8) * 2;
            }
            *(uint4*)dst = val;
        }
    }
    __syncthreads();

    if (rbase + w * 16 >= SEQ) return;       // fully-ghost warp (half1,w7)

    const uint32_t sb = smem_u32(fsm);
    const uint32_t QhU = sb + QH_OFF, KhU = sb + KH_OFF, VhU = sb + VH_OFF;

    const int row0g = rbase + w * 16 + grp;  // thread's row A (grp), row B = +8
    const int row1g = row0g + 8;
    const int nch = min(8 * half + w + 1, 15);   // 16-col k chunks (causal bound)

    // Q fragments (A, m16k16), hoisted: dk = 0..3 covers d 0..63
    uint32_t qf[4][4];
#pragma unroll
    for (int dk = 0; dk < 4; dk++)
        ldsm_x4(qf[dk], QhU + (uint32_t)((w * 16 + (lane & 15)) * PADH2
                                         + dk * 16 + ((lane >> 4) << 3)) * 2);

    float m0 = -1e30f, m1 = -1e30f, l0 = 0.f, l1 = 0.f;
    float acc[8][4];
#pragma unroll
    for (int nf = 0; nf < 8; nf++)
#pragma unroll
        for (int i = 0; i < 4; i++) acc[nf][i] = 0.f;

    const float sc = 1.0f / 32.0f;

    for (int kc = 0; kc < nch; kc++) {
        // ---- scores S[2 nfrag][4] for this 16-col chunk ----
        float S[2][4];
#pragma unroll
        for (int ng = 0; ng < 2; ng++)
#pragma unroll
            for (int i = 0; i < 4; i++) S[ng][i] = 0.f;

#pragma unroll
        for (int dg2 = 0; dg2 < 2; dg2++) {
#pragma unroll
            for (int ng = 0; ng < 2; ng++) {
                uint32_t kb[4];
                ldsm_x4(kb, KhU + (uint32_t)((kc * 16 + ng * 8 + (lane & 7)) * PADH2
                                             + dg2 * 32 + ((lane >> 3) << 3)) * 2);
                mma_f16(S[ng], qf[dg2 * 2 + 0], kb[0], kb[1]);
                mma_f16(S[ng], qf[dg2 * 2 + 1], kb[2], kb[3]);
            }
        }

        // ---- scale + causal mask ----
        float s_[2][4];
#pragma unroll
        for (int ng = 0; ng < 2; ng++) {
            int colb = kc * 16 + ng * 8 + 2 * qid;
            s_[ng][0] = (colb     <= row0g) ? S[ng][0] * sc : -1e30f;
            s_[ng][1] = (colb + 1 <= row0g) ? S[ng][1] * sc : -1e30f;
            s_[ng][2] = (colb     <= row1g) ? S[ng][2] * sc : -1e30f;
            s_[ng][3] = (colb + 1 <= row1g) ? S[ng][3] * sc : -1e30f;
        }

        // ---- online softmax (rows grp / grp+8) ----
        float mc0 = fmaxf(fmaxf(s_[0][0], s_[0][1]), fmaxf(s_[1][0], s_[1][1]));
        float mc1 = fmaxf(fmaxf(s_[0][2], s_[0][3]), fmaxf(s_[1][2], s_[1][3]));
        mc0 = fmaxf(mc0, __shfl_xor_sync(0xffffffff, mc0, 1));
        mc0 = fmaxf(mc0, __shfl_xor_sync(0xffffffff, mc0, 2));
        mc1 = fmaxf(mc1, __shfl_xor_sync(0xffffffff, mc1, 1));
        mc1 = fmaxf(mc1, __shfl_xor_sync(0xffffffff, mc1, 2));
        float m0n = fmaxf(m0, mc0), m1n = fmaxf(m1, mc1);
        float sf0 = __expf(m0 - m0n), sf1 = __expf(m1 - m1n);

        float p[2][4];
#pragma unroll
        for (int ng = 0; ng < 2; ng++) {
            p[ng][0] = __expf(s_[ng][0] - m0n);
            p[ng][1] = __expf(s_[ng][1] - m0n);
            p[ng][2] = __expf(s_[ng][2] - m1n);
            p[ng][3] = __expf(s_[ng][3] - m1n);
        }
        float rs0 = p[0][0] + p[0][1] + p[1][0] + p[1][1];
        float rs1 = p[0][2] + p[0][3] + p[1][2] + p[1][3];
        rs0 += __shfl_xor_sync(0xffffffff, rs0, 1);
        rs0 += __shfl_xor_sync(0xffffffff, rs0, 2);
        rs1 += __shfl_xor_sync(0xffffffff, rs1, 1);
        rs1 += __shfl_xor_sync(0xffffffff, rs1, 2);
        l0 = l0 * sf0 + rs0;  m0 = m0n;
        l1 = l1 * sf1 + rs1;  m1 = m1n;

        // ---- rescale output accumulators ----
#pragma unroll
        for (int nf = 0; nf < 8; nf++) {
            acc[nf][0] *= sf0; acc[nf][1] *= sf0;
            acc[nf][2] *= sf1; acc[nf][3] *= sf1;
        }

        // ---- P (fp16) as A-operand fragments (C->A layout reuse) ----
        uint32_t ap[4];
        {
            __half2 h0 = __floats2half2_rn(p[0][0], p[0][1]);
            __half2 h1 = __floats2half2_rn(p[0][2], p[0][3]);
            __half2 h2 = __floats2half2_rn(p[1][0], p[1][1]);
            __half2 h3 = __floats2half2_rn(p[1][2], p[1][3]);
            ap[0] = *(uint32_t*)&h0;
            ap[1] = *(uint32_t*)&h1;
            ap[2] = *(uint32_t*)&h2;
            ap[3] = *(uint32_t*)&h3;
        }

        // ---- PV: acc += P @ V_chunk ----
#pragma unroll
        for (int dg = 0; dg < 4; dg++) {
            uint32_t vb[4];
            ldsm_x4_t(vb, VhU + (uint32_t)((kc * 16 + (lane & 15)) * PADH2
                                           + dg * 16 + ((lane >> 4) << 3)) * 2);
            mma_f16(acc[2 * dg],     ap, vb[0], vb[1]);
            mma_f16(acc[2 * dg + 1], ap, vb[2], vb[3]);
        }
    }

    // ---- epilogue: normalize + padded-query zeroing + store ----
    float inv0 = (row0g < len) ? (1.0f / l0) : 0.0f;
    float inv1 = (row1g < len) ? (1.0f / l1) : 0.0f;
    float* ob0 = att + (long long)(b * SEQ + row0g) * HID + h * DHEAD;
    float* ob1 = att + (long long)(b * SEQ + row1g) * HID + h * DHEAD;
#pragma unroll
    for (int nf = 0; nf < 8; nf++) {
        int col = (nf >> 1) * 16 + (nf & 1) * 8 + 2 * qid;
        *(float2*)&ob0[col] = make_float2(acc[nf][0] * inv0, acc[nf][1] * inv0);
        *(float2*)&ob1[col] = make_float2(acc[nf][2] * inv1, acc[nf][3] * inv1);
    }
}

// ---------------- embedding: argmax + gather + posenc (fp32 + fp16 copy) ----------------
__global__ void embed_kernel(const float* __restrict__ x,
                             const float* __restrict__ w_emb,
                             const float* __restrict__ p_emb,
                             const int*   __restrict__ lengths) {
    int bs = blockIdx.x;
    int b = bs / SEQ, s = bs % SEQ;
    __shared__ int s_tok;
    int tid = threadIdx.x;
    if (tid < 32) {
        const float* xp = x + (long long)bs * NVOCAB;
        float bv = -1e30f; int bi = 0;
        for (int c = tid; c < NVOCAB; c += 32) {
            float v = xp[c];
            if (v > bv) { bv = v; bi = c; }
        }
        for (int off = 16; off > 0; off >>= 1) {
            float ov = __shfl_down_sync(0xffffffff, bv, off);
            int   oi = __shfl_down_sync(0xffffffff, bi, off);
            if (ov > bv || (ov == bv && oi < bi)) { bv = ov; bi = oi; }
        }
        if (tid == 0) s_tok = bi;
    }
    __syncthreads();
    int tok = s_tok;
    float valid = (s < lengths[b]) ? 1.0f : 0.0f;
    const float* we = w_emb + (long long)tok * HID;
    const float* pe = p_emb + (long long)s * HID;
    float*  zp  = g_z   + (long long)bs * HID;
    __half* zph = g_z16 + (long long)bs * HID;
    for (int h = tid; h < HID; h += blockDim.x) {
        float v = we[h] * valid + pe[h];
        zp[h]  = v;
        zph[h] = __float2half(v);
    }
}

// ---------------- residual add + LayerNorm (fp32 out + fp16 copy) ----------------
__global__ void add_ln_kernel(const float* __restrict__ a, const float* __restrict__ r,
                              const float* __restrict__ sc, const float* __restrict__ bi,
                              float* __restrict__ out, __half* __restrict__ out16) {
    int row = blockIdx.x;
    int tid = threadIdx.x;
    const float* ap = a + (long long)row * HID;
    const float* rp = r + (long long)row * HID;
    float v[4];
    float s = 0.f, sq = 0.f;
#pragma unroll
    for (int j = 0; j < 4; j++) {
        int h = tid + j*256;
        v[j] = ap[h] + rp[h];
        s  += v[j];
        sq += v[j]*v[j];
    }
    __shared__ float red1[8], red2[8];
    for (int off = 16; off > 0; off >>= 1) {
        s  += __shfl_xor_sync(0xffffffff, s,  off);
        sq += __shfl_xor_sync(0xffffffff, sq, off);
    }
    int warp = tid >> 5, lane = tid & 31;
    if (lane == 0) { red1[warp] = s; red2[warp] = sq; }
    __syncthreads();
    if (warp == 0) {
        s  = (lane < 8) ? red1[lane] : 0.f;
        sq = (lane < 8) ? red2[lane] : 0.f;
        for (int off = 4; off > 0; off >>= 1) {
            s  += __shfl_xor_sync(0xffffffff, s,  off);
            sq += __shfl_xor_sync(0xffffffff, sq, off);
        }
        if (lane == 0) { red1[0] = s; red2[0] = sq; }
    }
    __syncthreads();
    float mean = red1[0] * (1.0f / HID);
    float var  = red2[0] * (1.0f / HID) - mean * mean;
    float rstd = rsqrtf(var + 1e-5f);
    float*  op  = out   + (long long)row * HID;
    __half* oph = out16 + (long long)row * HID;
#pragma unroll
    for (int j = 0; j < 4; j++) {
        int h = tid + j*256;
        float o = (v[j] - mean) * rstd * sc[h] + bi[h];
        op[h]  = o;
        oph[h] = __float2half(o);
    }
}

// ---------------- mean-pool ----------------
__global__ void pool_kernel() {
    int b = blockIdx.y;
    int h = blockIdx.x * 256 + threadIdx.x;
    float s = 0.f;
    const float* zp = g_z + (long long)b * SEQ * HID + h;
    for (int si = 0; si < SEQ; si++)
        s += zp[(long long)si * HID];
    g_pool[b * HID + h] = s * (1.0f / SEQ);
}

// ---------------- classifier head + softmax(4) ----------------
__global__ void head_kernel(const float* __restrict__ Wfc, const float* __restrict__ bfc,
                            float* __restrict__ out) {
    int b = blockIdx.x;
    int tid = threadIdx.x;
    float p[4] = {0.f, 0.f, 0.f, 0.f};
    const float* zp = g_pool + b * HID;
    for (int h = tid; h < HID; h += 256) {
        float zv = zp[h];
#pragma unroll
        for (int c = 0; c < 4; c++) p[c] += zv * Wfc[h*4 + c];
    }
    __shared__ float red[4][256];
#pragma unroll
    for (int c = 0; c < 4; c++) red[c][tid] = p[c];
    __syncthreads();
    for (int str = 128; str > 0; str >>= 1) {
        if (tid < str)
#pragma unroll
            for (int c = 0; c < 4; c++) red[c][tid] += red[c][tid + str];
        __syncthreads();
    }
    if (tid == 0) {
        float l[4];
        float m = -1e30f;
#pragma unroll
        for (int c = 0; c < 4; c++) { l[c] = red[c][0] + bfc[c]; m = fmaxf(m, l[c]); }
        float ssum = 0.f;
#pragma unroll
        for (int c = 0; c < 4; c++) { l[c] = __expf(l[c] - m); ssum += l[c]; }
        float inv = 1.0f / ssum;
#pragma unroll
        for (int c = 0; c < 4; c++) out[b*4 + c] = l[c] * inv;
    }
}

// ---------------- host orchestration ----------------
extern "C" void kernel_launch(void* const* d_in, const int* in_sizes, int n_in,
                              void* d_out, int out_size) {
    const float* x     = (const float*)d_in[0];
    const float* w_emb = (const float*)d_in[1];
    const float* p_emb = (const float*)d_in[2];
    const float* Wq    = (const float*)d_in[3];
    const float* bq    = (const float*)d_in[4];
    const float* Wk    = (const float*)d_in[5];
    const float* bk    = (const float*)d_in[6];
    const float* Wv    = (const float*)d_in[7];
    const float* bv    = (const float*)d_in[8];
    const float* W1    = (const float*)d_in[9];
    const float* b1    = (const float*)d_in[10];
    const float* W2    = (const float*)d_in[11];
    const float* b2    = (const float*)d_in[12];
    const float* ln1_s = (const float*)d_in[13];
    const float* ln1_b = (const float*)d_in[14];
    const float* ln2_s = (const float*)d_in[15];
    const float* ln2_b = (const float*)d_in[16];
    const float* Wfc   = (const float*)d_in[17];
    const float* bfc   = (const float*)d_in[18];
    const int*   lengths = (const int*)d_in[19];
    float* out = (float*)d_out;

    float *pz, *patt, *pz1, *pbqkv;
    __half *pz16, *pz116, *pffh16, *pwqkv16, *pw1216, *pqkv16;
    cudaGetSymbolAddress((void**)&pz,     g_z);
    cudaGetSymbolAddress((void**)&pz16,   g_z16);
    cudaGetSymbolAddress((void**)&pqkv16, g_qkv16);
    cudaGetSymbolAddress((void**)&patt,   g_att);
    cudaGetSymbolAddress((void**)&pz1,    g_z1);
    cudaGetSymbolAddress((void**)&pz116,  g_z116);
    cudaGetSymbolAddress((void**)&pffh16, g_ffh16);
    cudaGetSymbolAddress((void**)&pwqkv16,g_wqkv16);
    cudaGetSymbolAddress((void**)&pw1216, g_w1216);
    cudaGetSymbolAddress((void**)&pbqkv,  g_bqkv);

    cudaFuncSetAttribute((const void*)gemm_h<0,0>, cudaFuncAttributeMaxDynamicSharedMemorySize, GEMM_SMEM);
    cudaFuncSetAttribute((const void*)gemm_h<0,1>, cudaFuncAttributeMaxDynamicSharedMemorySize, GEMM_SMEM);
    cudaFuncSetAttribute((const void*)gemm_h<1,1>, cudaFuncAttributeMaxDynamicSharedMemorySize, GEMM_SMEM);
    cudaFuncSetAttribute((const void*)flash_attn2, cudaFuncAttributeMaxDynamicSharedMemorySize, FA2_SMEM);

    const long long MAT = (long long)HID * HID;

    dim3 tgrid(HID/32, HID/32, NLAYER);
    dim3 tblk(32, 8);
    transpose_h_kernel<<<tgrid, tblk>>>(Wq, pwqkv16 + 0*MAT, 3*MAT);
    transpose_h_kernel<<<tgrid, tblk>>>(Wk, pwqkv16 + 1*MAT, 3*MAT);
    transpose_h_kernel<<<tgrid, tblk>>>(Wv, pwqkv16 + 2*MAT, 3*MAT);
    transpose_h_kernel<<<tgrid, tblk>>>(W1, pw1216  + 0*MAT, 2*MAT);
    transpose_h_kernel<<<tgrid, tblk>>>(W2, pw1216  + 1*MAT, 2*MAT);
    biaspack_kernel<<<(NLAYER*QKVW + 255)/256, 256>>>(bq, bk, bv);

    embed_kernel<<<BS_TOT, 256>>>(x, w_emb, p_emb, lengths);

    dim3 qkv_grid(QKVW/128, BS_TOT/128);   // (24, 60)
    dim3 ff_grid(HID/128, BS_TOT/128);     // (8, 60)
    dim3 fa_grid(NB*NHEAD, 2);             // (512, 2)

    for (int i = 0; i < NLAYER; i++) {
        long long bOff = (long long)i * HID;
        gemm_h<0,1><<<qkv_grid, 256, GEMM_SMEM>>>(pz16, pwqkv16 + (long long)i*3*MAT,
                                                  pbqkv + (long long)i*QKVW, pqkv16, QKVW);
        flash_attn2<<<fa_grid, 256, FA2_SMEM>>>(pqkv16, lengths, patt);
        add_ln_kernel<<<BS_TOT, 256>>>(pz, patt, ln1_s + bOff, ln1_b + bOff, pz1, pz116);
        gemm_h<1,1><<<ff_grid, 256, GEMM_SMEM>>>(pz116, pw1216 + (long long)i*2*MAT,
                                                 b1 + bOff, pffh16, HID);
        gemm_h<0,0><<<ff_grid, 256, GEMM_SMEM>>>(pffh16, pw1216 + (long long)i*2*MAT + MAT,
                                                 b2 + bOff, patt, HID);
        add_ln_kernel<<<BS_TOT, 256>>>(pz1, patt, ln2_s + bOff, ln2_b + bOff, pz, pz16);
    }

    pool_kernel<<<dim3(HID/256, NB), 256>>>();
    head_kernel<<<NB, 256>>>(Wfc, bfc, out);
}